// round 12
// baseline (speedup 1.0000x reference)
#include <cuda_runtime.h>
#include <cuda_bf16.h>
#include <math.h>
#include <stdint.h>

// ---------------------------------------------------------------------------
// GraphAE on GB300 (sm_103 plain target -> mma.sync tensor path).
// pseudo == 0 => only spline weight k=0 contributes.
// Activations as bf16 hi/lo plane pairs (hWr inter-stage tensor as fp32);
// 3-product compensated bf16 MMA (fp32 accum) == fp32-accurate GEMMs.
// Pipeline (5 launches):
//   CSRPREP (persistent hist->scan->place + weight prep, counter grid-sync)
//   -> agg1 -> FUSED[G1+G2] -> agg2 -> FUSED[G3+G4]
// ---------------------------------------------------------------------------

#define NNODES 50000
#define NEDGES 800000
#define NCSR_BLK 391           // CSR blocks: 8 edges/thread
#define NSEG 196               // scan segments of 256 nodes
#define NPREP_BLK 128          // weight-prep blocks

// ------------------------- scratch (static device) -------------------------
__device__ int   g_cnt[NNODES];        // zero-init (BSS); scan restores zero
__device__ int   g_rowptr[NNODES + 1];
__device__ int   g_cursor[NNODES];
__device__ int   g_csr[NEDGES];
__device__ float g_invdeg[NNODES];
__device__ int   g_bflag[NSEG];        // scan aggregates (sentinel +1); reset in-kernel
__device__ int   g_d1, g_d2, g_fin;    // phase counters; reset by last block

// activation planes (bf16 hi/lo) + fp32 hWr
__device__ __nv_bfloat16 g_A1h[(size_t)NNODES * 128], g_A1l[(size_t)NNODES * 128];
__device__ float         g_w[(size_t)NNODES * 128];   // hWr = [h@W2 | h@root2+b2]
__device__ __nv_bfloat16 g_zh[(size_t)NNODES * 64],   g_zl[(size_t)NNODES * 64];

// bf16 hi/lo split weights, natural [k][n] row-major
__device__ __nv_bfloat16 g_B1h[128 * 256], g_B1l[128 * 256];
__device__ __nv_bfloat16 g_B2h[256 * 128], g_B2l[256 * 128];
__device__ __nv_bfloat16 g_D1h[64 * 256],  g_D1l[64 * 256];
__device__ __nv_bfloat16 g_D2h[256 * 64],  g_D2l[256 * 64];
__device__ float g_b2c[128];                   // [0 | conv2_b]

// ------------------------------ helpers ------------------------------------
__device__ __forceinline__ uint32_t smem_u32(const void* p) {
    uint32_t a;
    asm("{ .reg .u64 t; cvta.to.shared.u64 t, %1; cvt.u32.u64 %0, t; }"
        : "=r"(a) : "l"(p));
    return a;
}
__device__ __forceinline__ void ldsm_x4(uint32_t* r, uint32_t addr) {
    asm volatile("ldmatrix.sync.aligned.m8n8.x4.shared.b16 {%0,%1,%2,%3}, [%4];"
                 : "=r"(r[0]), "=r"(r[1]), "=r"(r[2]), "=r"(r[3]) : "r"(addr));
}
__device__ __forceinline__ void ldsm_x4t(uint32_t* r, uint32_t addr) {
    asm volatile("ldmatrix.sync.aligned.m8n8.x4.trans.shared.b16 {%0,%1,%2,%3}, [%4];"
                 : "=r"(r[0]), "=r"(r[1]), "=r"(r[2]), "=r"(r[3]) : "r"(addr));
}
__device__ __forceinline__ void mma_bf16(float* d, const uint32_t* a,
                                         uint32_t b0, uint32_t b1) {
    asm volatile("mma.sync.aligned.m16n8k16.row.col.f32.bf16.bf16.f32 "
                 "{%0,%1,%2,%3}, {%4,%5,%6,%7}, {%8,%9}, {%0,%1,%2,%3};"
                 : "+f"(d[0]), "+f"(d[1]), "+f"(d[2]), "+f"(d[3])
                 : "r"(a[0]), "r"(a[1]), "r"(a[2]), "r"(a[3]), "r"(b0), "r"(b1));
}
__device__ __forceinline__ void cpa16(uint32_t dst, const void* src) {
    asm volatile("cp.async.cg.shared.global [%0], [%1], 16;"
                 :: "r"(dst), "l"(src));
}
#define CP_COMMIT() asm volatile("cp.async.commit_group;" ::: "memory")
#define CP_WAIT0()  asm volatile("cp.async.wait_group 0;" ::: "memory")
#define CP_WAIT1()  asm volatile("cp.async.wait_group 1;" ::: "memory")

__device__ __forceinline__ void split1(float v, uint16_t& h, uint16_t& l) {
    __nv_bfloat16 hb = __float2bfloat16_rn(v);
    float r = v - __bfloat162float(hb);
    __nv_bfloat16 lb = __float2bfloat16_rn(r);
    h = __bfloat16_as_ushort(hb);
    l = __bfloat16_as_ushort(lb);
}
__device__ __forceinline__ void split_pair(float a, float b, uint32_t& hp, uint32_t& lp) {
    uint16_t h0, l0, h1, l1;
    split1(a, h0, l0); split1(b, h1, l1);
    hp = (uint32_t)h0 | ((uint32_t)h1 << 16);
    lp = (uint32_t)l0 | ((uint32_t)l1 << 16);
}

// ------------- persistent CSR build (hist->scan->place) + prep -------------
// 391 CSR blocks (8 edges/thread, kept in regs across phases) + 128 prep
// blocks. All 519 blocks co-resident (<=64 regs, 4 blocks/SM) -> counter
// polls are deadlock-free. Counters/flags reset in-kernel for graph replay.
__global__ void __launch_bounds__(256, 4)
csrprep_k(const int* __restrict__ ei,
          const float* __restrict__ c1W, const float* __restrict__ c1r,
          const float* __restrict__ c2W, const float* __restrict__ c2r,
          const float* __restrict__ c2b,
          const float* __restrict__ dw1, const float* __restrict__ dw2) {
    const int b = blockIdx.x, tid = threadIdx.x;

    if (b >= NCSR_BLK) {                       // ---- weight prep blocks ----
        int i = (b - NCSR_BLK) * 256 + tid;
        uint16_t h, l;
        if (i < 128 * 256) {  // B1 [k=128][n=256]
            int k = i >> 8, n = i & 255;
            float v = (k < 64) ? c1W[k * 256 + n] : c1r[(k - 64) * 256 + n];
            split1(v, h, l);
            g_B1h[i] = __ushort_as_bfloat16(h); g_B1l[i] = __ushort_as_bfloat16(l);
        }
        if (i < 256 * 128) {  // B2 [k=256][n=128]
            int k = i >> 7, n = i & 127;
            float v = (n < 64) ? c2W[k * 64 + n] : c2r[k * 64 + (n - 64)];
            split1(v, h, l);
            g_B2h[i] = __ushort_as_bfloat16(h); g_B2l[i] = __ushort_as_bfloat16(l);
        }
        if (i < 64 * 256) {   // D1 [k=64][n=256]
            split1(dw1[i], h, l);
            g_D1h[i] = __ushort_as_bfloat16(h); g_D1l[i] = __ushort_as_bfloat16(l);
        }
        if (i < 256 * 64) {   // D2 [k=256][n=64]
            split1(dw2[i], h, l);
            g_D2h[i] = __ushort_as_bfloat16(h); g_D2l[i] = __ushort_as_bfloat16(l);
        }
        if (i < 128) g_b2c[i] = (i < 64) ? 0.0f : c2b[i - 64];
        return;
    }

    // ---------------- phase A: histogram (edges kept in regs) --------------
    const int e8 = (b * 256 + tid) * 8;
    const bool have = e8 < NEDGES;             // NEDGES % 8 == 0
    int4 d0, d1, s0, s1;
    if (have) {
        d0 = *(const int4*)(ei + NEDGES + e8);
        d1 = *(const int4*)(ei + NEDGES + e8 + 4);
        s0 = *(const int4*)(ei + e8);
        s1 = *(const int4*)(ei + e8 + 4);
        atomicAdd(&g_cnt[d0.x], 1); atomicAdd(&g_cnt[d0.y], 1);
        atomicAdd(&g_cnt[d0.z], 1); atomicAdd(&g_cnt[d0.w], 1);
        atomicAdd(&g_cnt[d1.x], 1); atomicAdd(&g_cnt[d1.y], 1);
        atomicAdd(&g_cnt[d1.z], 1); atomicAdd(&g_cnt[d1.w], 1);
    }
    __threadfence();
    __syncthreads();
    if (tid == 0) {
        atomicAdd(&g_d1, 1);
        while (atomicAdd(&g_d1, 0) < NCSR_BLK) {}
    }
    __syncthreads();
    __threadfence();

    // ---------------- phase B: scan (blocks 0..NSEG-1) ---------------------
    if (b < NSEG) {
        __shared__ int wsum[8];
        __shared__ int s_boff;
        int lane = tid & 31, w = tid >> 5;
        int i = b * 256 + tid;
        int v = (i < NNODES) ? g_cnt[i] : 0;
        int incl = v;
        #pragma unroll
        for (int o = 1; o < 32; o <<= 1) {
            int t2 = __shfl_up_sync(0xffffffff, incl, o);
            if (lane >= o) incl += t2;
        }
        if (lane == 31) wsum[w] = incl;
        if (tid == 0) s_boff = 0;
        __syncthreads();
        if (tid < 32) {
            int x2 = (tid < 8) ? wsum[tid] : 0;
            #pragma unroll
            for (int o = 1; o < 8; o <<= 1) {
                int t2 = __shfl_up_sync(0xffffffff, x2, o);
                if (tid >= o) x2 += t2;
            }
            if (tid < 8) wsum[tid] = x2;
        }
        __syncthreads();
        if (w > 0) incl += wsum[w - 1];
        if (tid == 255) atomicExch(&g_bflag[b], incl + 1);  // publish total
        if (tid < b) {                                      // poll predecessors
            int t2;
            do { t2 = atomicAdd(&g_bflag[tid], 0); } while (t2 == 0);
            atomicAdd(&s_boff, t2 - 1);
        }
        __syncthreads();
        int boff = s_boff;
        if (i < NNODES) {
            int start = boff + incl - v;
            g_rowptr[i] = start;
            g_cursor[i] = start;
            g_invdeg[i] = 1.0f / fmaxf((float)v, 1.0f);
            g_cnt[i] = 0;                      // restore for next replay
            if (i == NNODES - 1) g_rowptr[NNODES] = boff + incl;
        }
        __threadfence();
        __syncthreads();
        if (tid == 0) atomicAdd(&g_d2, 1);
    }
    if (tid == 0) {
        while (atomicAdd(&g_d2, 0) < NSEG) {}
    }
    __syncthreads();
    __threadfence();

    // ---------------- phase C: place (from registers) ----------------------
    if (have) {
        g_csr[atomicAdd(&g_cursor[d0.x], 1)] = s0.x;
        g_csr[atomicAdd(&g_cursor[d0.y], 1)] = s0.y;
        g_csr[atomicAdd(&g_cursor[d0.z], 1)] = s0.z;
        g_csr[atomicAdd(&g_cursor[d0.w], 1)] = s0.w;
        g_csr[atomicAdd(&g_cursor[d1.x], 1)] = s1.x;
        g_csr[atomicAdd(&g_cursor[d1.y], 1)] = s1.y;
        g_csr[atomicAdd(&g_cursor[d1.z], 1)] = s1.z;
        g_csr[atomicAdd(&g_cursor[d1.w], 1)] = s1.w;
    }
    if (b < NSEG && tid == 0) g_bflag[b] = 0;  // flags consumed; reset

    __threadfence();
    __syncthreads();
    if (tid == 0) {                             // last block resets counters
        int f = atomicAdd(&g_fin, 1);
        if (f == NCSR_BLK - 1) { g_d1 = 0; g_d2 = 0; g_fin = 0; }
    }
}

// --------------------------- gather aggregations ---------------------------
// warp per node; lane owns feature pair (2*lane, 2*lane+1); simple loop
// (R8-measured best: unrolling/half-warp variants regressed).
__global__ void agg1_k(const float* __restrict__ x) {
    int gt = blockIdx.x * blockDim.x + threadIdx.x;
    int node = gt >> 5;
    if (node >= NNODES) return;
    int lane = gt & 31;
    int beg = g_rowptr[node], end = g_rowptr[node + 1];
    float s0 = 0.f, s1 = 0.f;
    for (int i = beg; i < end; i++) {
        int s = g_csr[i];
        float2 v = __ldg((const float2*)(x + (size_t)s * 64 + 2 * lane));
        s0 += v.x; s1 += v.y;
    }
    float iv = g_invdeg[node];
    float2 xv = __ldg((const float2*)(x + (size_t)node * 64 + 2 * lane));
    uint32_t hp, lp;
    size_t o = (size_t)node * 128 + 2 * lane;
    split_pair(s0 * iv, s1 * iv, hp, lp);
    *(uint32_t*)(g_A1h + o) = hp; *(uint32_t*)(g_A1l + o) = lp;
    split_pair(xv.x, xv.y, hp, lp);
    *(uint32_t*)(g_A1h + o + 64) = hp; *(uint32_t*)(g_A1l + o + 64) = lp;
}

// z = gather(hW)*invdeg + hroot; hWr fp32: hW = cols 0:64, hroot = 64:128.
__global__ void agg2_k() {
    int gt = blockIdx.x * blockDim.x + threadIdx.x;
    int node = gt >> 5;
    if (node >= NNODES) return;
    int lane = gt & 31;
    int beg = g_rowptr[node], end = g_rowptr[node + 1];
    float s0 = 0.f, s1 = 0.f;
    for (int i = beg; i < end; i++) {
        int s = g_csr[i];
        float2 v = __ldg((const float2*)(g_w + (size_t)s * 128 + 2 * lane));
        s0 += v.x; s1 += v.y;
    }
    float iv = g_invdeg[node];
    float2 r = __ldg((const float2*)(g_w + (size_t)node * 128 + 64 + 2 * lane));
    float z0 = s0 * iv + r.x;
    float z1 = s1 * iv + r.y;
    uint32_t hp, lp;
    split_pair(z0, z1, hp, lp);
    size_t zo = (size_t)node * 64 + 2 * lane;
    *(uint32_t*)(g_zh + zo) = hp; *(uint32_t*)(g_zl + zo) = lp;
}

// -------------------- fused two-GEMM kernel (64-row tile) ------------------
// Phase1: T = relu(A[64,K1] @ B1[K1,N1=256] + bias1) -> split -> h smem
// Phase2: out = T @ B2[K2=N1,N2] + bias2 -> fp32 (g_w or final out)
// Double-buffered stages: phase1 buf1 aliases the (then-dead) h region; the
// last phase1 chunk is odd -> lives in buf1, dead exactly when the epilogue
// overwrites it. Phase2 double-buffers B2 in the dead phase1 stage region.
// 8 warps as 2(m) x 4(n); warp tile = 32 rows x N/4 cols. 3-product MMA.
template <int K1, int N1, int K2, int N2>
__global__ void __launch_bounds__(256, 2)
fused2_k(const __nv_bfloat16* __restrict__ Ah, const __nv_bfloat16* __restrict__ Al,
         const __nv_bfloat16* __restrict__ B1h, const __nv_bfloat16* __restrict__ B1l,
         const float* __restrict__ bias1,
         const __nv_bfloat16* __restrict__ B2h, const __nv_bfloat16* __restrict__ B2l,
         const float* __restrict__ bias2,
         float* __restrict__ Cf, int nRows) {
    static_assert(N1 == 256 && K2 == N1, "layout assumes N1=256");
    constexpr int KC = 32;
    constexpr int NCH1 = K1 / KC, NCH2 = K2 / KC;
    static_assert(NCH1 % 2 == 0, "last phase1 chunk must land in buf1");
    constexpr int WC1 = N1 / 4, NT1 = WC1 / 8, NTG1 = WC1 / 16;
    constexpr int WC2 = N2 / 4, NT2 = WC2 / 8, NTG2 = WC2 / 16;
    constexpr int SB1 = N1 + 8, SB2 = N2 + 8;
    constexpr int HST = 264;                       // h smem row stride (elems)
    constexpr int HPL = 64 * HST * 2;              // 33792 bytes per h plane
    constexpr int APL = 64 * 40 * 2;               // 5120 per A plane
    constexpr int ABUF = 2 * APL;                  // 10240
    constexpr int SBB1 = KC * SB1 * 2;             // B1 plane bytes (16896)
    constexpr int SBB2 = KC * SB2 * 2;
    constexpr int BUF0 = 2 * HPL;                  // 67584 (stage region)
    constexpr int BUF1 = 0;                        // aliases h planes (phase1)
    constexpr int P2B0 = BUF0;                     // phase2 B2 buffers
    constexpr int P2B1 = BUF0 + 2 * SBB2;

    extern __shared__ char dsm[];
    uint32_t sbase = smem_u32(dsm);

    const int tid = threadIdx.x;
    const int wid = tid >> 5, lane = tid & 31;
    const int wm = wid & 1, wn = wid >> 1;
    const int n0 = blockIdx.x * 64;
    int rem = nRows - n0;
    if (rem > 64) rem = 64;

    const int lrow = lane & 15, lhalf = lane >> 4;
    const int qr = lane >> 2, qc = (lane & 3) << 1;

    // stage A+B1 chunk c into buffer at 'buf'
    auto stage1 = [&](int c, uint32_t buf) {
        const int c0 = c * KC;
        {   // A: 64 rows x 32 cols, both planes (256 x 16B each)
            int row = tid >> 2, j = tid & 3;
            int gr = n0 + (row < rem ? row : rem - 1);
            uint32_t dst = sbase + buf + (uint32_t)(row * 80 + j * 16);
            cpa16(dst, (const char*)(Ah + (size_t)gr * K1 + c0) + j * 16);
            cpa16(dst + APL, (const char*)(Al + (size_t)gr * K1 + c0) + j * 16);
        }
        {   // B1: 32 rows x N1, both planes
            constexpr int G8 = N1 / 8;
            #pragma unroll
            for (int it = 0; it < KC * G8 / 256; it++) {
                int idx = it * 256 + tid;
                int row = idx / G8, g = idx - row * G8;
                uint32_t dst = sbase + buf + ABUF + (uint32_t)(row * (SB1 * 2) + g * 16);
                cpa16(dst, (const char*)(B1h + (size_t)(c0 + row) * N1) + g * 16);
                cpa16(dst + SBB1, (const char*)(B1l + (size_t)(c0 + row) * N1) + g * 16);
            }
        }
        CP_COMMIT();
    };
    auto stage2 = [&](int c, uint32_t buf) {
        const int c0 = c * KC;
        constexpr int G8 = N2 / 8;
        #pragma unroll
        for (int it = 0; it < (KC * G8 + 255) / 256; it++) {
            int idx = it * 256 + tid;
            if (KC * G8 % 256 == 0 || idx < KC * G8) {
                int row = idx / G8, g = idx - row * G8;
                uint32_t dst = sbase + buf + (uint32_t)(row * (SB2 * 2) + g * 16);
                cpa16(dst, (const char*)(B2h + (size_t)(c0 + row) * N2) + g * 16);
                cpa16(dst + SBB2, (const char*)(B2l + (size_t)(c0 + row) * N2) + g * 16);
            }
        }
        CP_COMMIT();
    };

    // =========================== phase 1 ===========================
    {
        const int col0 = wn * WC1;
        float acc[2][NT1][4];
        #pragma unroll
        for (int mt = 0; mt < 2; mt++)
            #pragma unroll
            for (int j = 0; j < NT1; j++)
                #pragma unroll
                for (int q = 0; q < 4; q++) acc[mt][j][q] = 0.f;

        stage1(0, BUF0);
        for (int c = 0; c < NCH1; c++) {
            if (c + 1 < NCH1) {
                stage1(c + 1, (c + 1) & 1 ? BUF1 : BUF0);
                CP_WAIT1();
            } else {
                CP_WAIT0();
            }
            __syncthreads();

            const uint32_t buf = (c & 1) ? BUF1 : BUF0;
            #pragma unroll
            for (int kk = 0; kk < KC; kk += 16) {
                uint32_t ah[2][4], al[2][4];
                #pragma unroll
                for (int mt = 0; mt < 2; mt++) {
                    uint32_t ra = sbase + buf +
                        (uint32_t)((32 * wm + 16 * mt + lrow) * 80 + kk * 2 + lhalf * 16);
                    ldsm_x4(ah[mt], ra);
                    ldsm_x4(al[mt], ra + APL);
                }
                #pragma unroll
                for (int ng = 0; ng < NTG1; ng++) {
                    uint32_t rb = sbase + buf + ABUF +
                        (uint32_t)(((kk + lrow) * SB1 + col0 + ng * 16) * 2 + lhalf * 16);
                    uint32_t bh[4], bl[4];
                    ldsm_x4t(bh, rb);
                    ldsm_x4t(bl, rb + SBB1);
                    #pragma unroll
                    for (int mt = 0; mt < 2; mt++) {
                        mma_bf16(acc[mt][2 * ng],     ah[mt], bh[0], bh[1]);
                        mma_bf16(acc[mt][2 * ng],     ah[mt], bl[0], bl[1]);
                        mma_bf16(acc[mt][2 * ng],     al[mt], bh[0], bh[1]);
                        mma_bf16(acc[mt][2 * ng + 1], ah[mt], bh[2], bh[3]);
                        mma_bf16(acc[mt][2 * ng + 1], ah[mt], bl[2], bl[3]);
                        mma_bf16(acc[mt][2 * ng + 1], al[mt], bh[2], bh[3]);
                    }
                }
            }
            __syncthreads();   // buffer free for restage / epilogue aliasing
        }

        // overlap: issue phase2 chunk 0 stage (BUF0 region is dead now)
        stage2(0, P2B0);

        // epilogue -> h smem planes (relu + split); overwrites BUF1 region
        #pragma unroll
        for (int mt = 0; mt < 2; mt++) {
            int row0 = 32 * wm + 16 * mt + qr;
            #pragma unroll
            for (int j = 0; j < NT1; j++) {
                int col = col0 + 8 * j + qc;
                float b0 = __ldg(&bias1[col]), b1 = __ldg(&bias1[col + 1]);
                float v00 = fmaxf(acc[mt][j][0] + b0, 0.f);
                float v01 = fmaxf(acc[mt][j][1] + b1, 0.f);
                float v10 = fmaxf(acc[mt][j][2] + b0, 0.f);
                float v11 = fmaxf(acc[mt][j][3] + b1, 0.f);
                uint32_t hp, lp;
                uint32_t o0 = (uint32_t)((row0 * HST + col) * 2);
                split_pair(v00, v01, hp, lp);
                *(uint32_t*)(dsm + o0) = hp;
                *(uint32_t*)(dsm + HPL + o0) = lp;
                uint32_t o1 = o0 + (uint32_t)(8 * HST * 2);
                split_pair(v10, v11, hp, lp);
                *(uint32_t*)(dsm + o1) = hp;
                *(uint32_t*)(dsm + HPL + o1) = lp;
            }
        }
    }
    __syncthreads();

    // =========================== phase 2 ===========================
    {
        const int col0 = wn * WC2;
        float acc[2][NT2][4];
        #pragma unroll
        for (int mt = 0; mt < 2; mt++)
            #pragma unroll
            for (int j = 0; j < NT2; j++)
                #pragma unroll
                for (int q = 0; q < 4; q++) acc[mt][j][q] = 0.f;

        for (int c = 0; c < NCH2; c++) {
            if (c + 1 < NCH2) {
                stage2(c + 1, (c + 1) & 1 ? P2B1 : P2B0);
                CP_WAIT1();
            } else {
                CP_WAIT0();
            }
            __syncthreads();

            const uint32_t buf = (c & 1) ? P2B1 : P2B0;
            const int c0 = c * KC;
            #pragma unroll
            for (int kk = 0; kk < KC; kk += 16) {
                uint32_t ah[2][4], al[2][4];
                #pragma unroll
                for (int mt = 0; mt < 2; mt++) {
                    uint32_t ra = sbase +
                        (uint32_t)(((32 * wm + 16 * mt + lrow) * HST + c0 + kk) * 2 + lhalf * 16);
                    ldsm_x4(ah[mt], ra);
                    ldsm_x4(al[mt], ra + HPL);
                }
                #pragma unroll
                for (int ng = 0; ng < NTG2; ng++) {
                    uint32_t rb = sbase + buf +
                        (uint32_t)(((kk + lrow) * SB2 + col0 + ng * 16) * 2 + lhalf * 16);
                    uint32_t bh[4], bl[4];
                    ldsm_x4t(bh, rb);
                    ldsm_x4t(bl, rb + SBB2);
                    #pragma unroll
                    for (int mt = 0; mt < 2; mt++) {
                        mma_bf16(acc[mt][2 * ng],     ah[mt], bh[0], bh[1]);
                        mma_bf16(acc[mt][2 * ng],     ah[mt], bl[0], bl[1]);
                        mma_bf16(acc[mt][2 * ng],     al[mt], bh[0], bh[1]);
                        mma_bf16(acc[mt][2 * ng + 1], ah[mt], bh[2], bh[3]);
                        mma_bf16(acc[mt][2 * ng + 1], ah[mt], bl[2], bl[3]);
                        mma_bf16(acc[mt][2 * ng + 1], al[mt], bh[2], bh[3]);
                    }
                }
            }
            if (c + 1 < NCH2) __syncthreads();
        }

        // epilogue -> global fp32
        #pragma unroll
        for (int mt = 0; mt < 2; mt++) {
            int row0 = 32 * wm + 16 * mt + qr;
            int row1 = row0 + 8;
            #pragma unroll
            for (int j = 0; j < NT2; j++) {
                int col = col0 + 8 * j + qc;
                float b0 = __ldg(&bias2[col]), b1 = __ldg(&bias2[col + 1]);
                float v00 = acc[mt][j][0] + b0, v01 = acc[mt][j][1] + b1;
                float v10 = acc[mt][j][2] + b0, v11 = acc[mt][j][3] + b1;
                if (row0 < rem)
                    *(float2*)(Cf + (size_t)(n0 + row0) * N2 + col) = make_float2(v00, v01);
                if (row1 < rem)
                    *(float2*)(Cf + (size_t)(n0 + row1) * N2 + col) = make_float2(v10, v11);
            }
        }
    }
}

// ------------------------------- launcher ----------------------------------
extern "C" void kernel_launch(void* const* d_in, const int* in_sizes, int n_in,
                              void* d_out, int out_size) {
    const float* x   = (const float*)d_in[0];
    const int*   ei  = (const int*)d_in[1];
    const float* c1W = (const float*)d_in[2];
    const float* c1r = (const float*)d_in[3];
    const float* c1b = (const float*)d_in[4];
    const float* c2W = (const float*)d_in[5];
    const float* c2r = (const float*)d_in[6];
    const float* c2b = (const float*)d_in[7];
    const float* dw1 = (const float*)d_in[8];
    const float* db1 = (const float*)d_in[9];
    const float* dw2 = (const float*)d_in[10];
    const float* db2 = (const float*)d_in[11];
    float* out = (float*)d_out;

    void *pB2c, *pW;
    void *pA1h, *pA1l, *pZh, *pZl;
    void *pB1h, *pB1l, *pB2h, *pB2l, *pD1h, *pD1l, *pD2h, *pD2l;
    cudaGetSymbolAddress(&pB2c, g_b2c);
    cudaGetSymbolAddress(&pW, g_w);
    cudaGetSymbolAddress(&pA1h, g_A1h); cudaGetSymbolAddress(&pA1l, g_A1l);
    cudaGetSymbolAddress(&pZh, g_zh);   cudaGetSymbolAddress(&pZl, g_zl);
    cudaGetSymbolAddress(&pB1h, g_B1h); cudaGetSymbolAddress(&pB1l, g_B1l);
    cudaGetSymbolAddress(&pB2h, g_B2h); cudaGetSymbolAddress(&pB2l, g_B2l);
    cudaGetSymbolAddress(&pD1h, g_D1h); cudaGetSymbolAddress(&pD1l, g_D1l);
    cudaGetSymbolAddress(&pD2h, g_D2h); cudaGetSymbolAddress(&pD2l, g_D2l);

    // smem: h planes 67584 + stage buf0 (A 10240 + B 33792) = 111616 -> occ 2
    const int SM_F = 67584 + 10240 + 33792;
    cudaFuncSetAttribute(fused2_k<128, 256, 256, 128>,
                         cudaFuncAttributeMaxDynamicSharedMemorySize, SM_F);
    cudaFuncSetAttribute(fused2_k<64, 256, 256, 64>,
                         cudaFuncAttributeMaxDynamicSharedMemorySize, SM_F);

    const int nFG = (NNODES + 63) / 64;                 // 782
    const int nAggBlocks = (NNODES * 32 + 255) / 256;   // 6250

    // --- persistent CSR build + weight prep (single launch) ---
    csrprep_k<<<NCSR_BLK + NPREP_BLK, 256>>>(ei, c1W, c1r, c2W, c2r, c2b, dw1, dw2);

    // --- conv1 input aggregation ---
    agg1_k<<<nAggBlocks, 256>>>(x);

    // --- fused conv1 GEMM + conv2 weight GEMM: A1 -> h(smem) -> hWr (fp32) ---
    fused2_k<128, 256, 256, 128><<<nFG, 256, SM_F>>>(
        (const __nv_bfloat16*)pA1h, (const __nv_bfloat16*)pA1l,
        (const __nv_bfloat16*)pB1h, (const __nv_bfloat16*)pB1l, c1b,
        (const __nv_bfloat16*)pB2h, (const __nv_bfloat16*)pB2l, (const float*)pB2c,
        (float*)pW, NNODES);

    // --- conv2 aggregation -> z planes ---
    agg2_k<<<nAggBlocks, 256>>>();

    // --- fused decoder: z -> h2(smem) -> out ---
    fused2_k<64, 256, 256, 64><<<nFG, 256, SM_F>>>(
        (const __nv_bfloat16*)pZh, (const __nv_bfloat16*)pZl,
        (const __nv_bfloat16*)pD1h, (const __nv_bfloat16*)pD1l, db1,
        (const __nv_bfloat16*)pD2h, (const __nv_bfloat16*)pD2l, db2,
        out, NNODES);
}

// round 13
// speedup vs baseline: 1.0142x; 1.0142x over previous
#include <cuda_runtime.h>
#include <cuda_bf16.h>
#include <math.h>
#include <stdint.h>

// ---------------------------------------------------------------------------
// GraphAE on GB300 (sm_103 plain target -> mma.sync tensor path).
// pseudo == 0 => only spline weight k=0 contributes.
// Activations as bf16 hi/lo plane pairs (hWr inter-stage tensor as fp32);
// 3-product compensated bf16 MMA (fp32 accum) == fp32-accurate GEMMs.
// Pipeline (7 launches):
//   hist+prep -> scanm -> place -> agg1 -> FUSED[G1+G2] -> agg2
//   -> FUSED[G3+G4]
// ---------------------------------------------------------------------------

#define NNODES 50000
#define NEDGES 800000
#define NB_SCAN 49
#define NHIST_BLK 391          // blocks doing histogram (8 edges/thread)
#define NPREP_BLK 128          // blocks doing weight prep

// ------------------------- scratch (static device) -------------------------
__device__ int   g_cnt[NNODES];        // zero-init (BSS); scanm restores zero
__device__ int   g_rowptr[NNODES + 1];
__device__ int   g_cursor[NNODES];
__device__ int   g_csr[NEDGES];
__device__ float g_invdeg[NNODES];
__device__ int   g_bflag[NB_SCAN];     // scan aggregates (sentinel +1); place zeroes

// activation planes (bf16 hi/lo) + fp32 hWr
__device__ __nv_bfloat16 g_A1h[(size_t)NNODES * 128], g_A1l[(size_t)NNODES * 128];
__device__ float         g_w[(size_t)NNODES * 128];   // hWr = [h@W2 | h@root2+b2]
__device__ __nv_bfloat16 g_zh[(size_t)NNODES * 64],   g_zl[(size_t)NNODES * 64];

// bf16 hi/lo split weights, natural [k][n] row-major
__device__ __nv_bfloat16 g_B1h[128 * 256], g_B1l[128 * 256];
__device__ __nv_bfloat16 g_B2h[256 * 128], g_B2l[256 * 128];
__device__ __nv_bfloat16 g_D1h[64 * 256],  g_D1l[64 * 256];
__device__ __nv_bfloat16 g_D2h[256 * 64],  g_D2l[256 * 64];
__device__ float g_b2c[128];                   // [0 | conv2_b]

// ------------------------------ helpers ------------------------------------
__device__ __forceinline__ uint32_t smem_u32(const void* p) {
    uint32_t a;
    asm("{ .reg .u64 t; cvta.to.shared.u64 t, %1; cvt.u32.u64 %0, t; }"
        : "=r"(a) : "l"(p));
    return a;
}
__device__ __forceinline__ void ldsm_x4(uint32_t* r, uint32_t addr) {
    asm volatile("ldmatrix.sync.aligned.m8n8.x4.shared.b16 {%0,%1,%2,%3}, [%4];"
                 : "=r"(r[0]), "=r"(r[1]), "=r"(r[2]), "=r"(r[3]) : "r"(addr));
}
__device__ __forceinline__ void ldsm_x4t(uint32_t* r, uint32_t addr) {
    asm volatile("ldmatrix.sync.aligned.m8n8.x4.trans.shared.b16 {%0,%1,%2,%3}, [%4];"
                 : "=r"(r[0]), "=r"(r[1]), "=r"(r[2]), "=r"(r[3]) : "r"(addr));
}
__device__ __forceinline__ void mma_bf16(float* d, const uint32_t* a,
                                         uint32_t b0, uint32_t b1) {
    asm volatile("mma.sync.aligned.m16n8k16.row.col.f32.bf16.bf16.f32 "
                 "{%0,%1,%2,%3}, {%4,%5,%6,%7}, {%8,%9}, {%0,%1,%2,%3};"
                 : "+f"(d[0]), "+f"(d[1]), "+f"(d[2]), "+f"(d[3])
                 : "r"(a[0]), "r"(a[1]), "r"(a[2]), "r"(a[3]), "r"(b0), "r"(b1));
}
__device__ __forceinline__ void cpa16(uint32_t dst, const void* src) {
    asm volatile("cp.async.cg.shared.global [%0], [%1], 16;"
                 :: "r"(dst), "l"(src));
}
#define CP_COMMIT() asm volatile("cp.async.commit_group;" ::: "memory")
#define CP_WAIT0()  asm volatile("cp.async.wait_group 0;" ::: "memory")
#define CP_WAIT1()  asm volatile("cp.async.wait_group 1;" ::: "memory")

__device__ __forceinline__ void split1(float v, uint16_t& h, uint16_t& l) {
    __nv_bfloat16 hb = __float2bfloat16_rn(v);
    float r = v - __bfloat162float(hb);
    __nv_bfloat16 lb = __float2bfloat16_rn(r);
    h = __bfloat16_as_ushort(hb);
    l = __bfloat16_as_ushort(lb);
}
__device__ __forceinline__ void split_pair(float a, float b, uint32_t& hp, uint32_t& lp) {
    uint16_t h0, l0, h1, l1;
    split1(a, h0, l0); split1(b, h1, l1);
    hp = (uint32_t)h0 | ((uint32_t)h1 << 16);
    lp = (uint32_t)l0 | ((uint32_t)l1 << 16);
}

// --------------------- fused histogram + weight prep -----------------------
__global__ void histprep_k(const int* __restrict__ ei,
                           const float* __restrict__ c1W, const float* __restrict__ c1r,
                           const float* __restrict__ c2W, const float* __restrict__ c2r,
                           const float* __restrict__ c2b,
                           const float* __restrict__ dw1, const float* __restrict__ dw2) {
    if (blockIdx.x < NHIST_BLK) {
        int e8 = (blockIdx.x * blockDim.x + threadIdx.x) * 8;
        if (e8 < NEDGES) {                     // NEDGES % 8 == 0
            int4 d0 = *(const int4*)(ei + NEDGES + e8);
            int4 d1 = *(const int4*)(ei + NEDGES + e8 + 4);
            atomicAdd(&g_cnt[d0.x], 1); atomicAdd(&g_cnt[d0.y], 1);
            atomicAdd(&g_cnt[d0.z], 1); atomicAdd(&g_cnt[d0.w], 1);
            atomicAdd(&g_cnt[d1.x], 1); atomicAdd(&g_cnt[d1.y], 1);
            atomicAdd(&g_cnt[d1.z], 1); atomicAdd(&g_cnt[d1.w], 1);
        }
        return;
    }
    int i = (blockIdx.x - NHIST_BLK) * blockDim.x + threadIdx.x;
    uint16_t h, l;
    if (i < 128 * 256) {  // B1 [k=128][n=256]
        int k = i >> 8, n = i & 255;
        float v = (k < 64) ? c1W[k * 256 + n] : c1r[(k - 64) * 256 + n];
        split1(v, h, l);
        g_B1h[i] = __ushort_as_bfloat16(h); g_B1l[i] = __ushort_as_bfloat16(l);
    }
    if (i < 256 * 128) {  // B2 [k=256][n=128]
        int k = i >> 7, n = i & 127;
        float v = (n < 64) ? c2W[k * 64 + n] : c2r[k * 64 + (n - 64)];
        split1(v, h, l);
        g_B2h[i] = __ushort_as_bfloat16(h); g_B2l[i] = __ushort_as_bfloat16(l);
    }
    if (i < 64 * 256) {   // D1 [k=64][n=256]
        split1(dw1[i], h, l);
        g_D1h[i] = __ushort_as_bfloat16(h); g_D1l[i] = __ushort_as_bfloat16(l);
    }
    if (i < 256 * 64) {   // D2 [k=256][n=64]
        split1(dw2[i], h, l);
        g_D2h[i] = __ushort_as_bfloat16(h); g_D2l[i] = __ushort_as_bfloat16(l);
    }
    if (i < 128) g_b2c[i] = (i < 64) ? 0.0f : c2b[i - 64];
}

// ------------------------------- CSR build ---------------------------------
// single-pass scan: 49 co-resident blocks, warp-shuffle local scan,
// cross-block offsets via published aggregates (sentinel = sum+1).
// Re-zeroes g_cnt; g_bflag is zeroed by place_k after use.
__global__ void scanm_k() {
    __shared__ int wsum[32];
    __shared__ int s_boff;
    int blk = blockIdx.x, tid = threadIdx.x;
    int i = blk * 1024 + tid;
    int v = (i < NNODES) ? g_cnt[i] : 0;
    int incl = v;
    #pragma unroll
    for (int o = 1; o < 32; o <<= 1) {
        int t = __shfl_up_sync(0xffffffff, incl, o);
        if ((tid & 31) >= o) incl += t;
    }
    if ((tid & 31) == 31) wsum[tid >> 5] = incl;
    if (tid == 0) s_boff = 0;
    __syncthreads();
    if (tid < 32) {
        int w = wsum[tid];
        #pragma unroll
        for (int o = 1; o < 32; o <<= 1) {
            int t = __shfl_up_sync(0xffffffff, w, o);
            if (tid >= o) w += t;
        }
        wsum[tid] = w;                         // inclusive warp sums
    }
    __syncthreads();
    if (tid >= 32) incl += wsum[(tid >> 5) - 1];
    if (tid == 1023) atomicExch(&g_bflag[blk], wsum[31] + 1);  // publish total
    if (tid < blk) {                                           // poll predecessors
        int t;
        do { t = atomicAdd(&g_bflag[tid], 0); } while (t == 0);
        atomicAdd(&s_boff, t - 1);
    }
    __syncthreads();
    int boff = s_boff;
    if (i < NNODES) {
        int start = boff + incl - v;
        g_rowptr[i] = start;
        g_cursor[i] = start;
        g_invdeg[i] = 1.0f / fmaxf((float)v, 1.0f);
        g_cnt[i] = 0;                          // restore for next replay
        if (i == NNODES - 1) g_rowptr[NNODES] = boff + incl;
    }
}

__global__ void place_k(const int* __restrict__ ei) {
    int t = blockIdx.x * blockDim.x + threadIdx.x;
    int e8 = t * 8;
    if (e8 < NEDGES) {
        int4 d0 = *(const int4*)(ei + NEDGES + e8);
        int4 d1 = *(const int4*)(ei + NEDGES + e8 + 4);
        int4 s0 = *(const int4*)(ei + e8);
        int4 s1 = *(const int4*)(ei + e8 + 4);
        g_csr[atomicAdd(&g_cursor[d0.x], 1)] = s0.x;
        g_csr[atomicAdd(&g_cursor[d0.y], 1)] = s0.y;
        g_csr[atomicAdd(&g_cursor[d0.z], 1)] = s0.z;
        g_csr[atomicAdd(&g_cursor[d0.w], 1)] = s0.w;
        g_csr[atomicAdd(&g_cursor[d1.x], 1)] = s1.x;
        g_csr[atomicAdd(&g_cursor[d1.y], 1)] = s1.y;
        g_csr[atomicAdd(&g_cursor[d1.z], 1)] = s1.z;
        g_csr[atomicAdd(&g_cursor[d1.w], 1)] = s1.w;
    }
    if (t < NB_SCAN) g_bflag[t] = 0;           // reset scan flags for next replay
}

// --------------------------- gather aggregations ---------------------------
// warp per node; lane owns feature pair (2*lane, 2*lane+1); simple loop
// (R8-measured best: unrolling/half-warp variants regressed).
__global__ void agg1_k(const float* __restrict__ x) {
    int gt = blockIdx.x * blockDim.x + threadIdx.x;
    int node = gt >> 5;
    if (node >= NNODES) return;
    int lane = gt & 31;
    int beg = g_rowptr[node], end = g_rowptr[node + 1];
    float s0 = 0.f, s1 = 0.f;
    for (int i = beg; i < end; i++) {
        int s = __ldcs(&g_csr[i]);             // stream CSR, keep x in L2
        float2 v = __ldg((const float2*)(x + (size_t)s * 64 + 2 * lane));
        s0 += v.x; s1 += v.y;
    }
    float iv = g_invdeg[node];
    float2 xv = __ldg((const float2*)(x + (size_t)node * 64 + 2 * lane));
    uint32_t hp, lp;
    size_t o = (size_t)node * 128 + 2 * lane;
    split_pair(s0 * iv, s1 * iv, hp, lp);
    *(uint32_t*)(g_A1h + o) = hp; *(uint32_t*)(g_A1l + o) = lp;
    split_pair(xv.x, xv.y, hp, lp);
    *(uint32_t*)(g_A1h + o + 64) = hp; *(uint32_t*)(g_A1l + o + 64) = lp;
}

// z = gather(hW)*invdeg + hroot; hWr fp32: hW = cols 0:64, hroot = 64:128.
__global__ void agg2_k() {
    int gt = blockIdx.x * blockDim.x + threadIdx.x;
    int node = gt >> 5;
    if (node >= NNODES) return;
    int lane = gt & 31;
    int beg = g_rowptr[node], end = g_rowptr[node + 1];
    float s0 = 0.f, s1 = 0.f;
    for (int i = beg; i < end; i++) {
        int s = __ldcs(&g_csr[i]);             // stream CSR, keep g_w in L2
        float2 v = __ldg((const float2*)(g_w + (size_t)s * 128 + 2 * lane));
        s0 += v.x; s1 += v.y;
    }
    float iv = g_invdeg[node];
    float2 r = __ldg((const float2*)(g_w + (size_t)node * 128 + 64 + 2 * lane));
    float z0 = s0 * iv + r.x;
    float z1 = s1 * iv + r.y;
    uint32_t hp, lp;
    split_pair(z0, z1, hp, lp);
    size_t zo = (size_t)node * 64 + 2 * lane;
    *(uint32_t*)(g_zh + zo) = hp; *(uint32_t*)(g_zl + zo) = lp;
}

// -------------------- fused two-GEMM kernel (64-row tile) ------------------
// Phase1: T = relu(A[64,K1] @ B1[K1,N1=256] + bias1) -> split -> h smem
// Phase2: out = T @ B2[K2=N1,N2] + bias2 -> fp32 (g_w or final out)
// Double-buffered stages: phase1 buf1 aliases the (then-dead) h region; the
// last phase1 chunk is odd -> lives in buf1, dead exactly when the epilogue
// overwrites it. Phase2 double-buffers B2 in the dead phase1 stage region.
// 8 warps as 2(m) x 4(n); warp tile = 32 rows x N/4 cols. 3-product MMA.
template <int K1, int N1, int K2, int N2>
__global__ void __launch_bounds__(256, 2)
fused2_k(const __nv_bfloat16* __restrict__ Ah, const __nv_bfloat16* __restrict__ Al,
         const __nv_bfloat16* __restrict__ B1h, const __nv_bfloat16* __restrict__ B1l,
         const float* __restrict__ bias1,
         const __nv_bfloat16* __restrict__ B2h, const __nv_bfloat16* __restrict__ B2l,
         const float* __restrict__ bias2,
         float* __restrict__ Cf, int nRows) {
    static_assert(N1 == 256 && K2 == N1, "layout assumes N1=256");
    constexpr int KC = 32;
    constexpr int NCH1 = K1 / KC, NCH2 = K2 / KC;
    static_assert(NCH1 % 2 == 0, "last phase1 chunk must land in buf1");
    constexpr int WC1 = N1 / 4, NT1 = WC1 / 8, NTG1 = WC1 / 16;
    constexpr int WC2 = N2 / 4, NT2 = WC2 / 8, NTG2 = WC2 / 16;
    constexpr int SB1 = N1 + 8, SB2 = N2 + 8;
    constexpr int HST = 264;                       // h smem row stride (elems)
    constexpr int HPL = 64 * HST * 2;              // 33792 bytes per h plane
    constexpr int APL = 64 * 40 * 2;               // 5120 per A plane
    constexpr int ABUF = 2 * APL;                  // 10240
    constexpr int SBB1 = KC * SB1 * 2;             // B1 plane bytes (16896)
    constexpr int SBB2 = KC * SB2 * 2;
    constexpr int BUF0 = 2 * HPL;                  // 67584 (stage region)
    constexpr int BUF1 = 0;                        // aliases h planes (phase1)
    constexpr int P2B0 = BUF0;                     // phase2 B2 buffers
    constexpr int P2B1 = BUF0 + 2 * SBB2;

    extern __shared__ char dsm[];
    uint32_t sbase = smem_u32(dsm);

    const int tid = threadIdx.x;
    const int wid = tid >> 5, lane = tid & 31;
    const int wm = wid & 1, wn = wid >> 1;
    const int n0 = blockIdx.x * 64;
    int rem = nRows - n0;
    if (rem > 64) rem = 64;

    const int lrow = lane & 15, lhalf = lane >> 4;
    const int qr = lane >> 2, qc = (lane & 3) << 1;

    // stage A+B1 chunk c into buffer at 'buf'
    auto stage1 = [&](int c, uint32_t buf) {
        const int c0 = c * KC;
        {   // A: 64 rows x 32 cols, both planes (256 x 16B each)
            int row = tid >> 2, j = tid & 3;
            int gr = n0 + (row < rem ? row : rem - 1);
            uint32_t dst = sbase + buf + (uint32_t)(row * 80 + j * 16);
            cpa16(dst, (const char*)(Ah + (size_t)gr * K1 + c0) + j * 16);
            cpa16(dst + APL, (const char*)(Al + (size_t)gr * K1 + c0) + j * 16);
        }
        {   // B1: 32 rows x N1, both planes
            constexpr int G8 = N1 / 8;
            #pragma unroll
            for (int it = 0; it < KC * G8 / 256; it++) {
                int idx = it * 256 + tid;
                int row = idx / G8, g = idx - row * G8;
                uint32_t dst = sbase + buf + ABUF + (uint32_t)(row * (SB1 * 2) + g * 16);
                cpa16(dst, (const char*)(B1h + (size_t)(c0 + row) * N1) + g * 16);
                cpa16(dst + SBB1, (const char*)(B1l + (size_t)(c0 + row) * N1) + g * 16);
            }
        }
        CP_COMMIT();
    };
    auto stage2 = [&](int c, uint32_t buf) {
        const int c0 = c * KC;
        constexpr int G8 = N2 / 8;
        #pragma unroll
        for (int it = 0; it < (KC * G8 + 255) / 256; it++) {
            int idx = it * 256 + tid;
            if (KC * G8 % 256 == 0 || idx < KC * G8) {
                int row = idx / G8, g = idx - row * G8;
                uint32_t dst = sbase + buf + (uint32_t)(row * (SB2 * 2) + g * 16);
                cpa16(dst, (const char*)(B2h + (size_t)(c0 + row) * N2) + g * 16);
                cpa16(dst + SBB2, (const char*)(B2l + (size_t)(c0 + row) * N2) + g * 16);
            }
        }
        CP_COMMIT();
    };

    // =========================== phase 1 ===========================
    {
        const int col0 = wn * WC1;
        float acc[2][NT1][4];
        #pragma unroll
        for (int mt = 0; mt < 2; mt++)
            #pragma unroll
            for (int j = 0; j < NT1; j++)
                #pragma unroll
                for (int q = 0; q < 4; q++) acc[mt][j][q] = 0.f;

        stage1(0, BUF0);
        for (int c = 0; c < NCH1; c++) {
            if (c + 1 < NCH1) {
                stage1(c + 1, (c + 1) & 1 ? BUF1 : BUF0);
                CP_WAIT1();
            } else {
                CP_WAIT0();
            }
            __syncthreads();

            const uint32_t buf = (c & 1) ? BUF1 : BUF0;
            #pragma unroll
            for (int kk = 0; kk < KC; kk += 16) {
                uint32_t ah[2][4], al[2][4];
                #pragma unroll
                for (int mt = 0; mt < 2; mt++) {
                    uint32_t ra = sbase + buf +
                        (uint32_t)((32 * wm + 16 * mt + lrow) * 80 + kk * 2 + lhalf * 16);
                    ldsm_x4(ah[mt], ra);
                    ldsm_x4(al[mt], ra + APL);
                }
                #pragma unroll
                for (int ng = 0; ng < NTG1; ng++) {
                    uint32_t rb = sbase + buf + ABUF +
                        (uint32_t)(((kk + lrow) * SB1 + col0 + ng * 16) * 2 + lhalf * 16);
                    uint32_t bh[4], bl[4];
                    ldsm_x4t(bh, rb);
                    ldsm_x4t(bl, rb + SBB1);
                    #pragma unroll
                    for (int mt = 0; mt < 2; mt++) {
                        mma_bf16(acc[mt][2 * ng],     ah[mt], bh[0], bh[1]);
                        mma_bf16(acc[mt][2 * ng],     ah[mt], bl[0], bl[1]);
                        mma_bf16(acc[mt][2 * ng],     al[mt], bh[0], bh[1]);
                        mma_bf16(acc[mt][2 * ng + 1], ah[mt], bh[2], bh[3]);
                        mma_bf16(acc[mt][2 * ng + 1], ah[mt], bl[2], bl[3]);
                        mma_bf16(acc[mt][2 * ng + 1], al[mt], bh[2], bh[3]);
                    }
                }
            }
            __syncthreads();   // buffer free for restage / epilogue aliasing
        }

        // overlap: issue phase2 chunk 0 stage (BUF0 region is dead now)
        stage2(0, P2B0);

        // epilogue -> h smem planes (relu + split); overwrites BUF1 region
        #pragma unroll
        for (int mt = 0; mt < 2; mt++) {
            int row0 = 32 * wm + 16 * mt + qr;
            #pragma unroll
            for (int j = 0; j < NT1; j++) {
                int col = col0 + 8 * j + qc;
                float b0 = __ldg(&bias1[col]), b1 = __ldg(&bias1[col + 1]);
                float v00 = fmaxf(acc[mt][j][0] + b0, 0.f);
                float v01 = fmaxf(acc[mt][j][1] + b1, 0.f);
                float v10 = fmaxf(acc[mt][j][2] + b0, 0.f);
                float v11 = fmaxf(acc[mt][j][3] + b1, 0.f);
                uint32_t hp, lp;
                uint32_t o0 = (uint32_t)((row0 * HST + col) * 2);
                split_pair(v00, v01, hp, lp);
                *(uint32_t*)(dsm + o0) = hp;
                *(uint32_t*)(dsm + HPL + o0) = lp;
                uint32_t o1 = o0 + (uint32_t)(8 * HST * 2);
                split_pair(v10, v11, hp, lp);
                *(uint32_t*)(dsm + o1) = hp;
                *(uint32_t*)(dsm + HPL + o1) = lp;
            }
        }
    }
    __syncthreads();

    // =========================== phase 2 ===========================
    {
        const int col0 = wn * WC2;
        float acc[2][NT2][4];
        #pragma unroll
        for (int mt = 0; mt < 2; mt++)
            #pragma unroll
            for (int j = 0; j < NT2; j++)
                #pragma unroll
                for (int q = 0; q < 4; q++) acc[mt][j][q] = 0.f;

        for (int c = 0; c < NCH2; c++) {
            if (c + 1 < NCH2) {
                stage2(c + 1, (c + 1) & 1 ? P2B1 : P2B0);
                CP_WAIT1();
            } else {
                CP_WAIT0();
            }
            __syncthreads();

            const uint32_t buf = (c & 1) ? P2B1 : P2B0;
            const int c0 = c * KC;
            #pragma unroll
            for (int kk = 0; kk < KC; kk += 16) {
                uint32_t ah[2][4], al[2][4];
                #pragma unroll
                for (int mt = 0; mt < 2; mt++) {
                    uint32_t ra = sbase +
                        (uint32_t)(((32 * wm + 16 * mt + lrow) * HST + c0 + kk) * 2 + lhalf * 16);
                    ldsm_x4(ah[mt], ra);
                    ldsm_x4(al[mt], ra + HPL);
                }
                #pragma unroll
                for (int ng = 0; ng < NTG2; ng++) {
                    uint32_t rb = sbase + buf +
                        (uint32_t)(((kk + lrow) * SB2 + col0 + ng * 16) * 2 + lhalf * 16);
                    uint32_t bh[4], bl[4];
                    ldsm_x4t(bh, rb);
                    ldsm_x4t(bl, rb + SBB2);
                    #pragma unroll
                    for (int mt = 0; mt < 2; mt++) {
                        mma_bf16(acc[mt][2 * ng],     ah[mt], bh[0], bh[1]);
                        mma_bf16(acc[mt][2 * ng],     ah[mt], bl[0], bl[1]);
                        mma_bf16(acc[mt][2 * ng],     al[mt], bh[0], bh[1]);
                        mma_bf16(acc[mt][2 * ng + 1], ah[mt], bh[2], bh[3]);
                        mma_bf16(acc[mt][2 * ng + 1], ah[mt], bl[2], bl[3]);
                        mma_bf16(acc[mt][2 * ng + 1], al[mt], bh[2], bh[3]);
                    }
                }
            }
            if (c + 1 < NCH2) __syncthreads();
        }

        // epilogue -> global fp32
        #pragma unroll
        for (int mt = 0; mt < 2; mt++) {
            int row0 = 32 * wm + 16 * mt + qr;
            int row1 = row0 + 8;
            #pragma unroll
            for (int j = 0; j < NT2; j++) {
                int col = col0 + 8 * j + qc;
                float b0 = __ldg(&bias2[col]), b1 = __ldg(&bias2[col + 1]);
                float v00 = acc[mt][j][0] + b0, v01 = acc[mt][j][1] + b1;
                float v10 = acc[mt][j][2] + b0, v11 = acc[mt][j][3] + b1;
                if (row0 < rem)
                    *(float2*)(Cf + (size_t)(n0 + row0) * N2 + col) = make_float2(v00, v01);
                if (row1 < rem)
                    *(float2*)(Cf + (size_t)(n0 + row1) * N2 + col) = make_float2(v10, v11);
            }
        }
    }
}

// ------------------------------- launcher ----------------------------------
extern "C" void kernel_launch(void* const* d_in, const int* in_sizes, int n_in,
                              void* d_out, int out_size) {
    const float* x   = (const float*)d_in[0];
    const int*   ei  = (const int*)d_in[1];
    const float* c1W = (const float*)d_in[2];
    const float* c1r = (const float*)d_in[3];
    const float* c1b = (const float*)d_in[4];
    const float* c2W = (const float*)d_in[5];
    const float* c2r = (const float*)d_in[6];
    const float* c2b = (const float*)d_in[7];
    const float* dw1 = (const float*)d_in[8];
    const float* db1 = (const float*)d_in[9];
    const float* dw2 = (const float*)d_in[10];
    const float* db2 = (const float*)d_in[11];
    float* out = (float*)d_out;

    void *pB2c, *pW;
    void *pA1h, *pA1l, *pZh, *pZl;
    void *pB1h, *pB1l, *pB2h, *pB2l, *pD1h, *pD1l, *pD2h, *pD2l;
    cudaGetSymbolAddress(&pB2c, g_b2c);
    cudaGetSymbolAddress(&pW, g_w);
    cudaGetSymbolAddress(&pA1h, g_A1h); cudaGetSymbolAddress(&pA1l, g_A1l);
    cudaGetSymbolAddress(&pZh, g_zh);   cudaGetSymbolAddress(&pZl, g_zl);
    cudaGetSymbolAddress(&pB1h, g_B1h); cudaGetSymbolAddress(&pB1l, g_B1l);
    cudaGetSymbolAddress(&pB2h, g_B2h); cudaGetSymbolAddress(&pB2l, g_B2l);
    cudaGetSymbolAddress(&pD1h, g_D1h); cudaGetSymbolAddress(&pD1l, g_D1l);
    cudaGetSymbolAddress(&pD2h, g_D2h); cudaGetSymbolAddress(&pD2l, g_D2l);

    // smem: h planes 67584 + stage buf0 (A 10240 + B 33792) = 111616 -> occ 2
    const int SM_F = 67584 + 10240 + 33792;
    cudaFuncSetAttribute(fused2_k<128, 256, 256, 128>,
                         cudaFuncAttributeMaxDynamicSharedMemorySize, SM_F);
    cudaFuncSetAttribute(fused2_k<64, 256, 256, 64>,
                         cudaFuncAttributeMaxDynamicSharedMemorySize, SM_F);

    const int nFG = (NNODES + 63) / 64;                 // 782
    const int nE8Blocks = (NEDGES / 8 + 255) / 256;     // 391
    const int nAggBlocks = (NNODES * 32 + 255) / 256;   // 6250

    // --- CSR build + weight prep (fused histogram/prep kernel) ---
    histprep_k<<<NHIST_BLK + NPREP_BLK, 256>>>(ei, c1W, c1r, c2W, c2r, c2b, dw1, dw2);
    scanm_k<<<NB_SCAN, 1024>>>();
    place_k<<<nE8Blocks, 256>>>(ei);

    // --- conv1 input aggregation ---
    agg1_k<<<nAggBlocks, 256>>>(x);

    // --- fused conv1 GEMM + conv2 weight GEMM: A1 -> h(smem) -> hWr (fp32) ---
    fused2_k<128, 256, 256, 128><<<nFG, 256, SM_F>>>(
        (const __nv_bfloat16*)pA1h, (const __nv_bfloat16*)pA1l,
        (const __nv_bfloat16*)pB1h, (const __nv_bfloat16*)pB1l, c1b,
        (const __nv_bfloat16*)pB2h, (const __nv_bfloat16*)pB2l, (const float*)pB2c,
        (float*)pW, NNODES);

    // --- conv2 aggregation -> z planes ---
    agg2_k<<<nAggBlocks, 256>>>();

    // --- fused decoder: z -> h2(smem) -> out ---
    fused2_k<64, 256, 256, 64><<<nFG, 256, SM_F>>>(
        (const __nv_bfloat16*)pZh, (const __nv_bfloat16*)pZl,
        (const __nv_bfloat16*)pD1h, (const __nv_bfloat16*)pD1l, db1,
        (const __nv_bfloat16*)pD2h, (const __nv_bfloat16*)pD2l, db2,
        out, NNODES);
}

// round 14
// speedup vs baseline: 1.0679x; 1.0529x over previous
#include <cuda_runtime.h>
#include <cuda_bf16.h>
#include <math.h>
#include <stdint.h>

// ---------------------------------------------------------------------------
// GraphAE on GB300 (sm_103 plain target -> mma.sync tensor path).
// pseudo == 0 => only spline weight k=0 contributes.
// Activations as bf16 hi/lo plane pairs (hWr inter-stage tensor as fp32);
// 3-product compensated bf16 MMA (fp32 accum) == fp32-accurate GEMMs.
// Pipeline (7 launches, PDL-chained):
//   hist+prep -> scanm -> place -> agg1 -> FUSED[G1+G2] -> agg2
//   -> FUSED[G3+G4]
// Each consumer does independent prologue work before
// cudaGridDependencySynchronize(), overlapping the producer's tail.
// ---------------------------------------------------------------------------

#define NNODES 50000
#define NEDGES 800000
#define NB_SCAN 49
#define NHIST_BLK 782          // blocks doing histogram (4 edges/thread)
#define NPREP_BLK 128          // blocks doing weight prep

// ------------------------- scratch (static device) -------------------------
__device__ int   g_cnt[NNODES];        // zero-init (BSS); scanm restores zero
__device__ int   g_rowptr[NNODES + 1];
__device__ int   g_cursor[NNODES];
__device__ int   g_csr[NEDGES];
__device__ float g_invdeg[NNODES];
__device__ int   g_bflag[NB_SCAN];     // scan aggregates (sentinel +1); place zeroes

// activation planes (bf16 hi/lo) + fp32 hWr
__device__ __nv_bfloat16 g_A1h[(size_t)NNODES * 128], g_A1l[(size_t)NNODES * 128];
__device__ float         g_w[(size_t)NNODES * 128];   // hWr = [h@W2 | h@root2+b2]
__device__ __nv_bfloat16 g_zh[(size_t)NNODES * 64],   g_zl[(size_t)NNODES * 64];

// bf16 hi/lo split weights, natural [k][n] row-major
__device__ __nv_bfloat16 g_B1h[128 * 256], g_B1l[128 * 256];
__device__ __nv_bfloat16 g_B2h[256 * 128], g_B2l[256 * 128];
__device__ __nv_bfloat16 g_D1h[64 * 256],  g_D1l[64 * 256];
__device__ __nv_bfloat16 g_D2h[256 * 64],  g_D2l[256 * 64];
__device__ float g_b2c[128];                   // [0 | conv2_b]

// ------------------------------ helpers ------------------------------------
__device__ __forceinline__ uint32_t smem_u32(const void* p) {
    uint32_t a;
    asm("{ .reg .u64 t; cvta.to.shared.u64 t, %1; cvt.u32.u64 %0, t; }"
        : "=r"(a) : "l"(p));
    return a;
}
__device__ __forceinline__ void ldsm_x4(uint32_t* r, uint32_t addr) {
    asm volatile("ldmatrix.sync.aligned.m8n8.x4.shared.b16 {%0,%1,%2,%3}, [%4];"
                 : "=r"(r[0]), "=r"(r[1]), "=r"(r[2]), "=r"(r[3]) : "r"(addr));
}
__device__ __forceinline__ void ldsm_x4t(uint32_t* r, uint32_t addr) {
    asm volatile("ldmatrix.sync.aligned.m8n8.x4.trans.shared.b16 {%0,%1,%2,%3}, [%4];"
                 : "=r"(r[0]), "=r"(r[1]), "=r"(r[2]), "=r"(r[3]) : "r"(addr));
}
__device__ __forceinline__ void mma_bf16(float* d, const uint32_t* a,
                                         uint32_t b0, uint32_t b1) {
    asm volatile("mma.sync.aligned.m16n8k16.row.col.f32.bf16.bf16.f32 "
                 "{%0,%1,%2,%3}, {%4,%5,%6,%7}, {%8,%9}, {%0,%1,%2,%3};"
                 : "+f"(d[0]), "+f"(d[1]), "+f"(d[2]), "+f"(d[3])
                 : "r"(a[0]), "r"(a[1]), "r"(a[2]), "r"(a[3]), "r"(b0), "r"(b1));
}
__device__ __forceinline__ void cpa16(uint32_t dst, const void* src) {
    asm volatile("cp.async.cg.shared.global [%0], [%1], 16;"
                 :: "r"(dst), "l"(src));
}
#define CP_COMMIT() asm volatile("cp.async.commit_group;" ::: "memory")
#define CP_WAIT0()  asm volatile("cp.async.wait_group 0;" ::: "memory")
#define CP_WAIT1()  asm volatile("cp.async.wait_group 1;" ::: "memory")

__device__ __forceinline__ void split1(float v, uint16_t& h, uint16_t& l) {
    __nv_bfloat16 hb = __float2bfloat16_rn(v);
    float r = v - __bfloat162float(hb);
    __nv_bfloat16 lb = __float2bfloat16_rn(r);
    h = __bfloat16_as_ushort(hb);
    l = __bfloat16_as_ushort(lb);
}
__device__ __forceinline__ void split_pair(float a, float b, uint32_t& hp, uint32_t& lp) {
    uint16_t h0, l0, h1, l1;
    split1(a, h0, l0); split1(b, h1, l1);
    hp = (uint32_t)h0 | ((uint32_t)h1 << 16);
    lp = (uint32_t)l0 | ((uint32_t)l1 << 16);
}

// --------------------- fused histogram + weight prep -----------------------
__global__ void histprep_k(const int* __restrict__ ei,
                           const float* __restrict__ c1W, const float* __restrict__ c1r,
                           const float* __restrict__ c2W, const float* __restrict__ c2r,
                           const float* __restrict__ c2b,
                           const float* __restrict__ dw1, const float* __restrict__ dw2) {
    if (blockIdx.x < NHIST_BLK) {
        int e4 = (blockIdx.x * blockDim.x + threadIdx.x) * 4;
        if (e4 < NEDGES) {
            int4 d = *(const int4*)(ei + NEDGES + e4);
            atomicAdd(&g_cnt[d.x], 1);
            atomicAdd(&g_cnt[d.y], 1);
            atomicAdd(&g_cnt[d.z], 1);
            atomicAdd(&g_cnt[d.w], 1);
        }
        return;
    }
    int i = (blockIdx.x - NHIST_BLK) * blockDim.x + threadIdx.x;
    uint16_t h, l;
    if (i < 128 * 256) {  // B1 [k=128][n=256]
        int k = i >> 8, n = i & 255;
        float v = (k < 64) ? c1W[k * 256 + n] : c1r[(k - 64) * 256 + n];
        split1(v, h, l);
        g_B1h[i] = __ushort_as_bfloat16(h); g_B1l[i] = __ushort_as_bfloat16(l);
    }
    if (i < 256 * 128) {  // B2 [k=256][n=128]
        int k = i >> 7, n = i & 127;
        float v = (n < 64) ? c2W[k * 64 + n] : c2r[k * 64 + (n - 64)];
        split1(v, h, l);
        g_B2h[i] = __ushort_as_bfloat16(h); g_B2l[i] = __ushort_as_bfloat16(l);
    }
    if (i < 64 * 256) {   // D1 [k=64][n=256]
        split1(dw1[i], h, l);
        g_D1h[i] = __ushort_as_bfloat16(h); g_D1l[i] = __ushort_as_bfloat16(l);
    }
    if (i < 256 * 64) {   // D2 [k=256][n=64]
        split1(dw2[i], h, l);
        g_D2h[i] = __ushort_as_bfloat16(h); g_D2l[i] = __ushort_as_bfloat16(l);
    }
    if (i < 128) g_b2c[i] = (i < 64) ? 0.0f : c2b[i - 64];
}

// ------------------------------- CSR build ---------------------------------
__global__ void scanm_k() {
    cudaGridDependencySynchronize();           // need g_cnt from histprep
    __shared__ int wsum[32];
    __shared__ int s_boff;
    int blk = blockIdx.x, tid = threadIdx.x;
    int i = blk * 1024 + tid;
    int v = (i < NNODES) ? g_cnt[i] : 0;
    int incl = v;
    #pragma unroll
    for (int o = 1; o < 32; o <<= 1) {
        int t = __shfl_up_sync(0xffffffff, incl, o);
        if ((tid & 31) >= o) incl += t;
    }
    if ((tid & 31) == 31) wsum[tid >> 5] = incl;
    if (tid == 0) s_boff = 0;
    __syncthreads();
    if (tid < 32) {
        int w = wsum[tid];
        #pragma unroll
        for (int o = 1; o < 32; o <<= 1) {
            int t = __shfl_up_sync(0xffffffff, w, o);
            if (tid >= o) w += t;
        }
        wsum[tid] = w;                         // inclusive warp sums
    }
    __syncthreads();
    if (tid >= 32) incl += wsum[(tid >> 5) - 1];
    if (tid == 1023) atomicExch(&g_bflag[blk], wsum[31] + 1);  // publish total
    if (tid < blk) {                                           // poll predecessors
        int t;
        do { t = atomicAdd(&g_bflag[tid], 0); } while (t == 0);
        atomicAdd(&s_boff, t - 1);
    }
    __syncthreads();
    int boff = s_boff;
    if (i < NNODES) {
        int start = boff + incl - v;
        g_rowptr[i] = start;
        g_cursor[i] = start;
        g_invdeg[i] = 1.0f / fmaxf((float)v, 1.0f);
        g_cnt[i] = 0;                          // restore for next replay
        if (i == NNODES - 1) g_rowptr[NNODES] = boff + incl;
    }
}

__global__ void place_k(const int* __restrict__ ei) {
    int t = blockIdx.x * blockDim.x + threadIdx.x;
    int e4 = t * 4;
    int4 d, s;
    if (e4 < NEDGES) {                         // prologue: edge loads (input)
        d = *(const int4*)(ei + NEDGES + e4);
        s = *(const int4*)(ei + e4);
    }
    cudaGridDependencySynchronize();           // need g_cursor from scanm
    if (e4 < NEDGES) {
        g_csr[atomicAdd(&g_cursor[d.x], 1)] = s.x;
        g_csr[atomicAdd(&g_cursor[d.y], 1)] = s.y;
        g_csr[atomicAdd(&g_cursor[d.z], 1)] = s.z;
        g_csr[atomicAdd(&g_cursor[d.w], 1)] = s.w;
    }
    if (t < NB_SCAN) g_bflag[t] = 0;           // reset scan flags for next replay
}

// --------------------------- gather aggregations ---------------------------
// warp per node; lane owns feature pair (2*lane, 2*lane+1); simple loop
// (R8-measured best: unrolling/half-warp variants regressed).
__global__ void agg1_k(const float* __restrict__ x) {
    int gt = blockIdx.x * blockDim.x + threadIdx.x;
    int node = gt >> 5;
    int lane = gt & 31;
    float2 xv = make_float2(0.f, 0.f);
    if (node < NNODES)                          // prologue: own x row (input)
        xv = __ldg((const float2*)(x + (size_t)node * 64 + 2 * lane));
    cudaGridDependencySynchronize();            // need rowptr/csr from place
    if (node >= NNODES) return;
    int beg = g_rowptr[node], end = g_rowptr[node + 1];
    float s0 = 0.f, s1 = 0.f;
    for (int i = beg; i < end; i++) {
        int s = g_csr[i];
        float2 v = __ldg((const float2*)(x + (size_t)s * 64 + 2 * lane));
        s0 += v.x; s1 += v.y;
    }
    float iv = g_invdeg[node];
    uint32_t hp, lp;
    size_t o = (size_t)node * 128 + 2 * lane;
    split_pair(s0 * iv, s1 * iv, hp, lp);
    *(uint32_t*)(g_A1h + o) = hp; *(uint32_t*)(g_A1l + o) = lp;
    split_pair(xv.x, xv.y, hp, lp);
    *(uint32_t*)(g_A1h + o + 64) = hp; *(uint32_t*)(g_A1l + o + 64) = lp;
}

// z = gather(hW)*invdeg + hroot; hWr fp32: hW = cols 0:64, hroot = 64:128.
__global__ void agg2_k() {
    cudaGridDependencySynchronize();            // need g_w from fused1
    int gt = blockIdx.x * blockDim.x + threadIdx.x;
    int node = gt >> 5;
    if (node >= NNODES) return;
    int lane = gt & 31;
    int beg = g_rowptr[node], end = g_rowptr[node + 1];
    float s0 = 0.f, s1 = 0.f;
    for (int i = beg; i < end; i++) {
        int s = g_csr[i];
        float2 v = __ldg((const float2*)(g_w + (size_t)s * 128 + 2 * lane));
        s0 += v.x; s1 += v.y;
    }
    float iv = g_invdeg[node];
    float2 r = __ldg((const float2*)(g_w + (size_t)node * 128 + 64 + 2 * lane));
    float z0 = s0 * iv + r.x;
    float z1 = s1 * iv + r.y;
    uint32_t hp, lp;
    split_pair(z0, z1, hp, lp);
    size_t zo = (size_t)node * 64 + 2 * lane;
    *(uint32_t*)(g_zh + zo) = hp; *(uint32_t*)(g_zl + zo) = lp;
}

// -------------------- fused two-GEMM kernel (64-row tile) ------------------
// Phase1: T = relu(A[64,K1] @ B1[K1,N1=256] + bias1) -> split -> h smem
// Phase2: out = T @ B2[K2=N1,N2] + bias2 -> fp32 (g_w or final out)
// Double-buffered stages; phase1 buf1 aliases the (then-dead) h region.
// PDL: B1 chunk-0 weights staged BEFORE the grid-dependency sync (they don't
// depend on the producer kernel); A stage after.
template <int K1, int N1, int K2, int N2>
__global__ void __launch_bounds__(256, 2)
fused2_k(const __nv_bfloat16* __restrict__ Ah, const __nv_bfloat16* __restrict__ Al,
         const __nv_bfloat16* __restrict__ B1h, const __nv_bfloat16* __restrict__ B1l,
         const float* __restrict__ bias1,
         const __nv_bfloat16* __restrict__ B2h, const __nv_bfloat16* __restrict__ B2l,
         const float* __restrict__ bias2,
         float* __restrict__ Cf, int nRows) {
    static_assert(N1 == 256 && K2 == N1, "layout assumes N1=256");
    constexpr int KC = 32;
    constexpr int NCH1 = K1 / KC, NCH2 = K2 / KC;
    static_assert(NCH1 % 2 == 0, "last phase1 chunk must land in buf1");
    constexpr int WC1 = N1 / 4, NT1 = WC1 / 8, NTG1 = WC1 / 16;
    constexpr int WC2 = N2 / 4, NT2 = WC2 / 8, NTG2 = WC2 / 16;
    constexpr int SB1 = N1 + 8, SB2 = N2 + 8;
    constexpr int HST = 264;                       // h smem row stride (elems)
    constexpr int HPL = 64 * HST * 2;              // 33792 bytes per h plane
    constexpr int APL = 64 * 40 * 2;               // 5120 per A plane
    constexpr int ABUF = 2 * APL;                  // 10240
    constexpr int SBB1 = KC * SB1 * 2;             // B1 plane bytes (16896)
    constexpr int SBB2 = KC * SB2 * 2;
    constexpr int BUF0 = 2 * HPL;                  // 67584 (stage region)
    constexpr int BUF1 = 0;                        // aliases h planes (phase1)
    constexpr int P2B0 = BUF0;                     // phase2 B2 buffers
    constexpr int P2B1 = BUF0 + 2 * SBB2;

    extern __shared__ char dsm[];
    uint32_t sbase = smem_u32(dsm);

    const int tid = threadIdx.x;
    const int wid = tid >> 5, lane = tid & 31;
    const int wm = wid & 1, wn = wid >> 1;
    const int n0 = blockIdx.x * 64;
    int rem = nRows - n0;
    if (rem > 64) rem = 64;

    const int lrow = lane & 15, lhalf = lane >> 4;
    const int qr = lane >> 2, qc = (lane & 3) << 1;

    // stage A of chunk c (depends on producer output)
    auto stageA = [&](int c, uint32_t buf) {
        const int c0 = c * KC;
        int row = tid >> 2, j = tid & 3;
        int gr = n0 + (row < rem ? row : rem - 1);
        uint32_t dst = sbase + buf + (uint32_t)(row * 80 + j * 16);
        cpa16(dst, (const char*)(Ah + (size_t)gr * K1 + c0) + j * 16);
        cpa16(dst + APL, (const char*)(Al + (size_t)gr * K1 + c0) + j * 16);
    };
    // stage B1 of chunk c (weights; independent of producer)
    auto stageB = [&](int c, uint32_t buf) {
        const int c0 = c * KC;
        constexpr int G8 = N1 / 8;
        #pragma unroll
        for (int it = 0; it < KC * G8 / 256; it++) {
            int idx = it * 256 + tid;
            int row = idx / G8, g = idx - row * G8;
            uint32_t dst = sbase + buf + ABUF + (uint32_t)(row * (SB1 * 2) + g * 16);
            cpa16(dst, (const char*)(B1h + (size_t)(c0 + row) * N1) + g * 16);
            cpa16(dst + SBB1, (const char*)(B1l + (size_t)(c0 + row) * N1) + g * 16);
        }
    };
    auto stage2 = [&](int c, uint32_t buf) {
        const int c0 = c * KC;
        constexpr int G8 = N2 / 8;
        #pragma unroll
        for (int it = 0; it < (KC * G8 + 255) / 256; it++) {
            int idx = it * 256 + tid;
            if (KC * G8 % 256 == 0 || idx < KC * G8) {
                int row = idx / G8, g = idx - row * G8;
                uint32_t dst = sbase + buf + (uint32_t)(row * (SB2 * 2) + g * 16);
                cpa16(dst, (const char*)(B2h + (size_t)(c0 + row) * N2) + g * 16);
                cpa16(dst + SBB2, (const char*)(B2l + (size_t)(c0 + row) * N2) + g * 16);
            }
        }
        CP_COMMIT();
    };

    // PDL prologue: stage chunk-0 weights while the producer finishes.
    stageB(0, BUF0);
    cudaGridDependencySynchronize();               // A-operand now visible
    stageA(0, BUF0);
    CP_COMMIT();

    // =========================== phase 1 ===========================
    {
        const int col0 = wn * WC1;
        float acc[2][NT1][4];
        #pragma unroll
        for (int mt = 0; mt < 2; mt++)
            #pragma unroll
            for (int j = 0; j < NT1; j++)
                #pragma unroll
                for (int q = 0; q < 4; q++) acc[mt][j][q] = 0.f;

        for (int c = 0; c < NCH1; c++) {
            if (c + 1 < NCH1) {
                uint32_t nb = (c + 1) & 1 ? BUF1 : BUF0;
                stageB(c + 1, nb);
                stageA(c + 1, nb);
                CP_COMMIT();
                CP_WAIT1();
            } else {
                CP_WAIT0();
            }
            __syncthreads();

            const uint32_t buf = (c & 1) ? BUF1 : BUF0;
            #pragma unroll
            for (int kk = 0; kk < KC; kk += 16) {
                uint32_t ah[2][4], al[2][4];
                #pragma unroll
                for (int mt = 0; mt < 2; mt++) {
                    uint32_t ra = sbase + buf +
                        (uint32_t)((32 * wm + 16 * mt + lrow) * 80 + kk * 2 + lhalf * 16);
                    ldsm_x4(ah[mt], ra);
                    ldsm_x4(al[mt], ra + APL);
                }
                #pragma unroll
                for (int ng = 0; ng < NTG1; ng++) {
                    uint32_t rb = sbase + buf + ABUF +
                        (uint32_t)(((kk + lrow) * SB1 + col0 + ng * 16) * 2 + lhalf * 16);
                    uint32_t bh[4], bl[4];
                    ldsm_x4t(bh, rb);
                    ldsm_x4t(bl, rb + SBB1);
                    #pragma unroll
                    for (int mt = 0; mt < 2; mt++) {
                        mma_bf16(acc[mt][2 * ng],     ah[mt], bh[0], bh[1]);
                        mma_bf16(acc[mt][2 * ng],     ah[mt], bl[0], bl[1]);
                        mma_bf16(acc[mt][2 * ng],     al[mt], bh[0], bh[1]);
                        mma_bf16(acc[mt][2 * ng + 1], ah[mt], bh[2], bh[3]);
                        mma_bf16(acc[mt][2 * ng + 1], ah[mt], bl[2], bl[3]);
                        mma_bf16(acc[mt][2 * ng + 1], al[mt], bh[2], bh[3]);
                    }
                }
            }
            __syncthreads();   // buffer free for restage / epilogue aliasing
        }

        // overlap: issue phase2 chunk 0 stage (BUF0 region is dead now)
        stage2(0, P2B0);

        // epilogue -> h smem planes (relu + split); overwrites BUF1 region
        #pragma unroll
        for (int mt = 0; mt < 2; mt++) {
            int row0 = 32 * wm + 16 * mt + qr;
            #pragma unroll
            for (int j = 0; j < NT1; j++) {
                int col = col0 + 8 * j + qc;
                float b0 = __ldg(&bias1[col]), b1 = __ldg(&bias1[col + 1]);
                float v00 = fmaxf(acc[mt][j][0] + b0, 0.f);
                float v01 = fmaxf(acc[mt][j][1] + b1, 0.f);
                float v10 = fmaxf(acc[mt][j][2] + b0, 0.f);
                float v11 = fmaxf(acc[mt][j][3] + b1, 0.f);
                uint32_t hp, lp;
                uint32_t o0 = (uint32_t)((row0 * HST + col) * 2);
                split_pair(v00, v01, hp, lp);
                *(uint32_t*)(dsm + o0) = hp;
                *(uint32_t*)(dsm + HPL + o0) = lp;
                uint32_t o1 = o0 + (uint32_t)(8 * HST * 2);
                split_pair(v10, v11, hp, lp);
                *(uint32_t*)(dsm + o1) = hp;
                *(uint32_t*)(dsm + HPL + o1) = lp;
            }
        }
    }
    __syncthreads();

    // =========================== phase 2 ===========================
    {
        const int col0 = wn * WC2;
        float acc[2][NT2][4];
        #pragma unroll
        for (int mt = 0; mt < 2; mt++)
            #pragma unroll
            for (int j = 0; j < NT2; j++)
                #pragma unroll
                for (int q = 0; q < 4; q++) acc[mt][j][q] = 0.f;

        for (int c = 0; c < NCH2; c++) {
            if (c + 1 < NCH2) {
                stage2(c + 1, (c + 1) & 1 ? P2B1 : P2B0);
                CP_WAIT1();
            } else {
                CP_WAIT0();
            }
            __syncthreads();

            const uint32_t buf = (c & 1) ? P2B1 : P2B0;
            const int c0 = c * KC;
            #pragma unroll
            for (int kk = 0; kk < KC; kk += 16) {
                uint32_t ah[2][4], al[2][4];
                #pragma unroll
                for (int mt = 0; mt < 2; mt++) {
                    uint32_t ra = sbase +
                        (uint32_t)(((32 * wm + 16 * mt + lrow) * HST + c0 + kk) * 2 + lhalf * 16);
                    ldsm_x4(ah[mt], ra);
                    ldsm_x4(al[mt], ra + HPL);
                }
                #pragma unroll
                for (int ng = 0; ng < NTG2; ng++) {
                    uint32_t rb = sbase + buf +
                        (uint32_t)(((kk + lrow) * SB2 + col0 + ng * 16) * 2 + lhalf * 16);
                    uint32_t bh[4], bl[4];
                    ldsm_x4t(bh, rb);
                    ldsm_x4t(bl, rb + SBB2);
                    #pragma unroll
                    for (int mt = 0; mt < 2; mt++) {
                        mma_bf16(acc[mt][2 * ng],     ah[mt], bh[0], bh[1]);
                        mma_bf16(acc[mt][2 * ng],     ah[mt], bl[0], bl[1]);
                        mma_bf16(acc[mt][2 * ng],     al[mt], bh[0], bh[1]);
                        mma_bf16(acc[mt][2 * ng + 1], ah[mt], bh[2], bh[3]);
                        mma_bf16(acc[mt][2 * ng + 1], ah[mt], bl[2], bl[3]);
                        mma_bf16(acc[mt][2 * ng + 1], al[mt], bh[2], bh[3]);
                    }
                }
            }
            if (c + 1 < NCH2) __syncthreads();
        }

        // epilogue -> global fp32
        #pragma unroll
        for (int mt = 0; mt < 2; mt++) {
            int row0 = 32 * wm + 16 * mt + qr;
            int row1 = row0 + 8;
            #pragma unroll
            for (int j = 0; j < NT2; j++) {
                int col = col0 + 8 * j + qc;
                float b0 = __ldg(&bias2[col]), b1 = __ldg(&bias2[col + 1]);
                float v00 = acc[mt][j][0] + b0, v01 = acc[mt][j][1] + b1;
                float v10 = acc[mt][j][2] + b0, v11 = acc[mt][j][3] + b1;
                if (row0 < rem)
                    *(float2*)(Cf + (size_t)(n0 + row0) * N2 + col) = make_float2(v00, v01);
                if (row1 < rem)
                    *(float2*)(Cf + (size_t)(n0 + row1) * N2 + col) = make_float2(v10, v11);
            }
        }
    }
}

// ------------------------------- launcher ----------------------------------
extern "C" void kernel_launch(void* const* d_in, const int* in_sizes, int n_in,
                              void* d_out, int out_size) {
    const float* x   = (const float*)d_in[0];
    const int*   ei  = (const int*)d_in[1];
    const float* c1W = (const float*)d_in[2];
    const float* c1r = (const float*)d_in[3];
    const float* c1b = (const float*)d_in[4];
    const float* c2W = (const float*)d_in[5];
    const float* c2r = (const float*)d_in[6];
    const float* c2b = (const float*)d_in[7];
    const float* dw1 = (const float*)d_in[8];
    const float* db1 = (const float*)d_in[9];
    const float* dw2 = (const float*)d_in[10];
    const float* db2 = (const float*)d_in[11];
    float* out = (float*)d_out;

    void *pB2c, *pW;
    void *pA1h, *pA1l, *pZh, *pZl;
    void *pB1h, *pB1l, *pB2h, *pB2l, *pD1h, *pD1l, *pD2h, *pD2l;
    cudaGetSymbolAddress(&pB2c, g_b2c);
    cudaGetSymbolAddress(&pW, g_w);
    cudaGetSymbolAddress(&pA1h, g_A1h); cudaGetSymbolAddress(&pA1l, g_A1l);
    cudaGetSymbolAddress(&pZh, g_zh);   cudaGetSymbolAddress(&pZl, g_zl);
    cudaGetSymbolAddress(&pB1h, g_B1h); cudaGetSymbolAddress(&pB1l, g_B1l);
    cudaGetSymbolAddress(&pB2h, g_B2h); cudaGetSymbolAddress(&pB2l, g_B2l);
    cudaGetSymbolAddress(&pD1h, g_D1h); cudaGetSymbolAddress(&pD1l, g_D1l);
    cudaGetSymbolAddress(&pD2h, g_D2h); cudaGetSymbolAddress(&pD2l, g_D2l);

    // smem: h planes 67584 + stage buf0 (A 10240 + B 33792) = 111616 -> occ 2
    const int SM_F = 67584 + 10240 + 33792;
    cudaFuncSetAttribute(fused2_k<128, 256, 256, 128>,
                         cudaFuncAttributeMaxDynamicSharedMemorySize, SM_F);
    cudaFuncSetAttribute(fused2_k<64, 256, 256, 64>,
                         cudaFuncAttributeMaxDynamicSharedMemorySize, SM_F);

    const int nFG = (NNODES + 63) / 64;                 // 782
    const int nE4Blocks = (NEDGES / 4 + 255) / 256;     // 782
    const int nAggBlocks = (NNODES * 32 + 255) / 256;   // 6250

    // PDL launch config: allow overlap with previous kernel in stream;
    // consumers order themselves via cudaGridDependencySynchronize().
    cudaLaunchAttribute at[1];
    at[0].id = cudaLaunchAttributeProgrammaticStreamSerialization;
    at[0].val.programmaticStreamSerializationAllowed = 1;
    cudaLaunchConfig_t cfg{};
    cfg.blockDim = {256, 1, 1};
    cfg.attrs = at;
    cfg.numAttrs = 1;

    // --- CSR build + weight prep ---
    cfg.gridDim = {NHIST_BLK + NPREP_BLK, 1, 1};
    cfg.dynamicSmemBytes = 0;
    cudaLaunchKernelEx(&cfg, histprep_k, ei, c1W, c1r, c2W, c2r, c2b, dw1, dw2);
    {
        cudaLaunchConfig_t c2 = cfg;
        c2.gridDim = {NB_SCAN, 1, 1};
        c2.blockDim = {1024, 1, 1};
        cudaLaunchKernelEx(&c2, scanm_k);
    }
    cfg.gridDim = {(unsigned)nE4Blocks, 1, 1};
    cudaLaunchKernelEx(&cfg, place_k, ei);

    // --- conv1 input aggregation ---
    cfg.gridDim = {(unsigned)nAggBlocks, 1, 1};
    cudaLaunchKernelEx(&cfg, agg1_k, x);

    // --- fused conv1 GEMM + conv2 weight GEMM: A1 -> h(smem) -> hWr (fp32) ---
    cfg.gridDim = {(unsigned)nFG, 1, 1};
    cfg.dynamicSmemBytes = SM_F;
    cudaLaunchKernelEx(&cfg, fused2_k<128, 256, 256, 128>,
        (const __nv_bfloat16*)pA1h, (const __nv_bfloat16*)pA1l,
        (const __nv_bfloat16*)pB1h, (const __nv_bfloat16*)pB1l, (const float*)c1b,
        (const __nv_bfloat16*)pB2h, (const __nv_bfloat16*)pB2l, (const float*)pB2c,
        (float*)pW, (int)NNODES);

    // --- conv2 aggregation -> z planes ---
    cfg.gridDim = {(unsigned)nAggBlocks, 1, 1};
    cfg.dynamicSmemBytes = 0;
    cudaLaunchKernelEx(&cfg, agg2_k);

    // --- fused decoder: z -> h2(smem) -> out ---
    cfg.gridDim = {(unsigned)nFG, 1, 1};
    cfg.dynamicSmemBytes = SM_F;
    cudaLaunchKernelEx(&cfg, fused2_k<64, 256, 256, 64>,
        (const __nv_bfloat16*)pZh, (const __nv_bfloat16*)pZl,
        (const __nv_bfloat16*)pD1h, (const __nv_bfloat16*)pD1l, (const float*)db1,
        (const __nv_bfloat16*)pD2h, (const __nv_bfloat16*)pD2l, (const float*)db2,
        out, (int)NNODES);
}

// round 15
// speedup vs baseline: 1.2909x; 1.2088x over previous
#include <cuda_runtime.h>
#include <cuda_fp16.h>
#include <math.h>
#include <stdint.h>

// ---------------------------------------------------------------------------
// GraphAE on GB300 (sm_103 plain target -> mma.sync tensor path).
// pseudo == 0 => only spline weight k=0 contributes.
// Activations as fp16 hi/lo plane pairs (22-bit effective); weights single
// fp16. GEMM: D = Ah*B + Al*B (2 MMAs, fp32 accum). Weight quantization
// ~2^-12/layer is the only non-fp32 error (budget: ~3e-4 vs 1e-3 threshold).
// Pipeline (7 launches, PDL-chained):
//   hist+prep -> scanm -> place -> agg1 -> FUSED[G1+G2] -> agg2
//   -> FUSED[G3+G4]
// ---------------------------------------------------------------------------

#define NNODES 50000
#define NEDGES 800000
#define NB_SCAN 49
#define NHIST_BLK 782          // blocks doing histogram (4 edges/thread)
#define NPREP_BLK 128          // blocks doing weight prep

// ------------------------- scratch (static device) -------------------------
__device__ int   g_cnt[NNODES];        // zero-init (BSS); scanm restores zero
__device__ int   g_rowptr[NNODES + 1];
__device__ int   g_cursor[NNODES];
__device__ int   g_csr[NEDGES];
__device__ float g_invdeg[NNODES];
__device__ int   g_bflag[NB_SCAN];     // scan aggregates (sentinel +1); place zeroes

// activation planes (fp16 hi/lo) + fp32 hWr
__device__ __half g_A1h[(size_t)NNODES * 128], g_A1l[(size_t)NNODES * 128];
__device__ float  g_w[(size_t)NNODES * 128];   // hWr = [h@W2 | h@root2+b2]
__device__ __half g_zh[(size_t)NNODES * 64],   g_zl[(size_t)NNODES * 64];

// fp16 weights, natural [k][n] row-major (single plane)
__device__ __half g_B1f[128 * 256];
__device__ __half g_B2f[256 * 128];
__device__ __half g_D1f[64 * 256];
__device__ __half g_D2f[256 * 64];
__device__ float g_b2c[128];                   // [0 | conv2_b]

// ------------------------------ helpers ------------------------------------
__device__ __forceinline__ uint32_t smem_u32(const void* p) {
    uint32_t a;
    asm("{ .reg .u64 t; cvta.to.shared.u64 t, %1; cvt.u32.u64 %0, t; }"
        : "=r"(a) : "l"(p));
    return a;
}
__device__ __forceinline__ void ldsm_x4(uint32_t* r, uint32_t addr) {
    asm volatile("ldmatrix.sync.aligned.m8n8.x4.shared.b16 {%0,%1,%2,%3}, [%4];"
                 : "=r"(r[0]), "=r"(r[1]), "=r"(r[2]), "=r"(r[3]) : "r"(addr));
}
__device__ __forceinline__ void ldsm_x4t(uint32_t* r, uint32_t addr) {
    asm volatile("ldmatrix.sync.aligned.m8n8.x4.trans.shared.b16 {%0,%1,%2,%3}, [%4];"
                 : "=r"(r[0]), "=r"(r[1]), "=r"(r[2]), "=r"(r[3]) : "r"(addr));
}
__device__ __forceinline__ void mma_f16(float* d, const uint32_t* a,
                                        uint32_t b0, uint32_t b1) {
    asm volatile("mma.sync.aligned.m16n8k16.row.col.f32.f16.f16.f32 "
                 "{%0,%1,%2,%3}, {%4,%5,%6,%7}, {%8,%9}, {%0,%1,%2,%3};"
                 : "+f"(d[0]), "+f"(d[1]), "+f"(d[2]), "+f"(d[3])
                 : "r"(a[0]), "r"(a[1]), "r"(a[2]), "r"(a[3]), "r"(b0), "r"(b1));
}
__device__ __forceinline__ void cpa16(uint32_t dst, const void* src) {
    asm volatile("cp.async.cg.shared.global [%0], [%1], 16;"
                 :: "r"(dst), "l"(src));
}
#define CP_COMMIT() asm volatile("cp.async.commit_group;" ::: "memory")
#define CP_WAIT0()  asm volatile("cp.async.wait_group 0;" ::: "memory")
#define CP_WAIT1()  asm volatile("cp.async.wait_group 1;" ::: "memory")

__device__ __forceinline__ void split1(float v, uint16_t& h, uint16_t& l) {
    __half hh = __float2half_rn(v);
    float r = v - __half2float(hh);
    __half hl = __float2half_rn(r);
    h = __half_as_ushort(hh);
    l = __half_as_ushort(hl);
}
__device__ __forceinline__ void split_pair(float a, float b, uint32_t& hp, uint32_t& lp) {
    uint16_t h0, l0, h1, l1;
    split1(a, h0, l0); split1(b, h1, l1);
    hp = (uint32_t)h0 | ((uint32_t)h1 << 16);
    lp = (uint32_t)l0 | ((uint32_t)l1 << 16);
}

// --------------------- fused histogram + weight prep -----------------------
__global__ void histprep_k(const int* __restrict__ ei,
                           const float* __restrict__ c1W, const float* __restrict__ c1r,
                           const float* __restrict__ c2W, const float* __restrict__ c2r,
                           const float* __restrict__ c2b,
                           const float* __restrict__ dw1, const float* __restrict__ dw2) {
    if (blockIdx.x < NHIST_BLK) {
        int e4 = (blockIdx.x * blockDim.x + threadIdx.x) * 4;
        if (e4 < NEDGES) {
            int4 d = *(const int4*)(ei + NEDGES + e4);
            atomicAdd(&g_cnt[d.x], 1);
            atomicAdd(&g_cnt[d.y], 1);
            atomicAdd(&g_cnt[d.z], 1);
            atomicAdd(&g_cnt[d.w], 1);
        }
        return;
    }
    int i = (blockIdx.x - NHIST_BLK) * blockDim.x + threadIdx.x;
    if (i < 128 * 256) {  // B1 [k=128][n=256]
        int k = i >> 8, n = i & 255;
        float v = (k < 64) ? c1W[k * 256 + n] : c1r[(k - 64) * 256 + n];
        g_B1f[i] = __float2half_rn(v);
    }
    if (i < 256 * 128) {  // B2 [k=256][n=128]
        int k = i >> 7, n = i & 127;
        float v = (n < 64) ? c2W[k * 64 + n] : c2r[k * 64 + (n - 64)];
        g_B2f[i] = __float2half_rn(v);
    }
    if (i < 64 * 256)  g_D1f[i] = __float2half_rn(dw1[i]);
    if (i < 256 * 64)  g_D2f[i] = __float2half_rn(dw2[i]);
    if (i < 128) g_b2c[i] = (i < 64) ? 0.0f : c2b[i - 64];
}

// ------------------------------- CSR build ---------------------------------
__global__ void scanm_k() {
    cudaGridDependencySynchronize();           // need g_cnt from histprep
    __shared__ int wsum[32];
    __shared__ int s_boff;
    int blk = blockIdx.x, tid = threadIdx.x;
    int i = blk * 1024 + tid;
    int v = (i < NNODES) ? g_cnt[i] : 0;
    int incl = v;
    #pragma unroll
    for (int o = 1; o < 32; o <<= 1) {
        int t = __shfl_up_sync(0xffffffff, incl, o);
        if ((tid & 31) >= o) incl += t;
    }
    if ((tid & 31) == 31) wsum[tid >> 5] = incl;
    if (tid == 0) s_boff = 0;
    __syncthreads();
    if (tid < 32) {
        int w = wsum[tid];
        #pragma unroll
        for (int o = 1; o < 32; o <<= 1) {
            int t = __shfl_up_sync(0xffffffff, w, o);
            if (tid >= o) w += t;
        }
        wsum[tid] = w;                         // inclusive warp sums
    }
    __syncthreads();
    if (tid >= 32) incl += wsum[(tid >> 5) - 1];
    if (tid == 1023) atomicExch(&g_bflag[blk], wsum[31] + 1);  // publish total
    if (tid < blk) {                                           // poll predecessors
        int t;
        do { t = atomicAdd(&g_bflag[tid], 0); } while (t == 0);
        atomicAdd(&s_boff, t - 1);
    }
    __syncthreads();
    int boff = s_boff;
    if (i < NNODES) {
        int start = boff + incl - v;
        g_rowptr[i] = start;
        g_cursor[i] = start;
        g_invdeg[i] = 1.0f / fmaxf((float)v, 1.0f);
        g_cnt[i] = 0;                          // restore for next replay
        if (i == NNODES - 1) g_rowptr[NNODES] = boff + incl;
    }
}

__global__ void place_k(const int* __restrict__ ei) {
    int t = blockIdx.x * blockDim.x + threadIdx.x;
    int e4 = t * 4;
    int4 d, s;
    if (e4 < NEDGES) {                         // prologue: edge loads (input)
        d = *(const int4*)(ei + NEDGES + e4);
        s = *(const int4*)(ei + e4);
    }
    cudaGridDependencySynchronize();           // need g_cursor from scanm
    if (e4 < NEDGES) {
        g_csr[atomicAdd(&g_cursor[d.x], 1)] = s.x;
        g_csr[atomicAdd(&g_cursor[d.y], 1)] = s.y;
        g_csr[atomicAdd(&g_cursor[d.z], 1)] = s.z;
        g_csr[atomicAdd(&g_cursor[d.w], 1)] = s.w;
    }
    if (t < NB_SCAN) g_bflag[t] = 0;           // reset scan flags for next replay
}

// --------------------------- gather aggregations ---------------------------
// warp per node; lane owns feature pair (2*lane, 2*lane+1); simple loop
// (R8-measured best: unrolling/half-warp variants regressed).
__global__ void agg1_k(const float* __restrict__ x) {
    int gt = blockIdx.x * blockDim.x + threadIdx.x;
    int node = gt >> 5;
    int lane = gt & 31;
    float2 xv = make_float2(0.f, 0.f);
    if (node < NNODES)                          // prologue: own x row (input)
        xv = __ldg((const float2*)(x + (size_t)node * 64 + 2 * lane));
    cudaGridDependencySynchronize();            // need rowptr/csr from place
    if (node >= NNODES) return;
    int beg = g_rowptr[node], end = g_rowptr[node + 1];
    float s0 = 0.f, s1 = 0.f;
    for (int i = beg; i < end; i++) {
        int s = g_csr[i];
        float2 v = __ldg((const float2*)(x + (size_t)s * 64 + 2 * lane));
        s0 += v.x; s1 += v.y;
    }
    float iv = g_invdeg[node];
    uint32_t hp, lp;
    size_t o = (size_t)node * 128 + 2 * lane;
    split_pair(s0 * iv, s1 * iv, hp, lp);
    *(uint32_t*)(g_A1h + o) = hp; *(uint32_t*)(g_A1l + o) = lp;
    split_pair(xv.x, xv.y, hp, lp);
    *(uint32_t*)(g_A1h + o + 64) = hp; *(uint32_t*)(g_A1l + o + 64) = lp;
}

// z = gather(hW)*invdeg + hroot; hWr fp32: hW = cols 0:64, hroot = 64:128.
__global__ void agg2_k() {
    cudaGridDependencySynchronize();            // need g_w from fused1
    int gt = blockIdx.x * blockDim.x + threadIdx.x;
    int node = gt >> 5;
    if (node >= NNODES) return;
    int lane = gt & 31;
    int beg = g_rowptr[node], end = g_rowptr[node + 1];
    float s0 = 0.f, s1 = 0.f;
    for (int i = beg; i < end; i++) {
        int s = g_csr[i];
        float2 v = __ldg((const float2*)(g_w + (size_t)s * 128 + 2 * lane));
        s0 += v.x; s1 += v.y;
    }
    float iv = g_invdeg[node];
    float2 r = __ldg((const float2*)(g_w + (size_t)node * 128 + 64 + 2 * lane));
    float z0 = s0 * iv + r.x;
    float z1 = s1 * iv + r.y;
    uint32_t hp, lp;
    split_pair(z0, z1, hp, lp);
    size_t zo = (size_t)node * 64 + 2 * lane;
    *(uint32_t*)(g_zh + zo) = hp; *(uint32_t*)(g_zl + zo) = lp;
}

// -------------------- fused two-GEMM kernel (64-row tile) ------------------
// Phase1: T = relu(A[64,K1] @ B1[K1,N1=256] + bias1) -> split -> h smem
// Phase2: out = T @ B2[K2=N1,N2] + bias2 -> fp32 (g_w or final out)
// 2-product fp16 MMA: acc += Ah*B + Al*B (B single fp16 plane).
// Double-buffered stages; phase1 buf1 aliases the (then-dead) h region.
// PDL: B1 chunk-0 weights staged BEFORE the grid-dependency sync.
template <int K1, int N1, int K2, int N2>
__global__ void __launch_bounds__(256, 2)
fused2_k(const __half* __restrict__ Ah, const __half* __restrict__ Al,
         const __half* __restrict__ B1f, const float* __restrict__ bias1,
         const __half* __restrict__ B2f, const float* __restrict__ bias2,
         float* __restrict__ Cf, int nRows) {
    static_assert(N1 == 256 && K2 == N1, "layout assumes N1=256");
    constexpr int KC = 32;
    constexpr int NCH1 = K1 / KC, NCH2 = K2 / KC;
    static_assert(NCH1 % 2 == 0, "last phase1 chunk must land in buf1");
    constexpr int WC1 = N1 / 4, NT1 = WC1 / 8, NTG1 = WC1 / 16;
    constexpr int WC2 = N2 / 4, NT2 = WC2 / 8, NTG2 = WC2 / 16;
    constexpr int SB1 = N1 + 8, SB2 = N2 + 8;
    constexpr int HST = 264;                       // h smem row stride (elems)
    constexpr int HPL = 64 * HST * 2;              // 33792 bytes per h plane
    constexpr int APL = 64 * 40 * 2;               // 5120 per A plane
    constexpr int ABUF = 2 * APL;                  // 10240
    constexpr int SBB1 = KC * SB1 * 2;             // B1 plane bytes (16896)
    constexpr int SBB2 = KC * SB2 * 2;
    constexpr int BUF0 = 2 * HPL;                  // 67584 (stage region)
    constexpr int BUF1 = 0;                        // aliases h planes (phase1)
    constexpr int P2B0 = BUF0;                     // phase2 B2 buffers
    constexpr int P2B1 = BUF0 + SBB2;

    extern __shared__ char dsm[];
    uint32_t sbase = smem_u32(dsm);

    const int tid = threadIdx.x;
    const int wid = tid >> 5, lane = tid & 31;
    const int wm = wid & 1, wn = wid >> 1;
    const int n0 = blockIdx.x * 64;
    int rem = nRows - n0;
    if (rem > 64) rem = 64;

    const int lrow = lane & 15, lhalf = lane >> 4;
    const int qr = lane >> 2, qc = (lane & 3) << 1;

    // stage A of chunk c (depends on producer output)
    auto stageA = [&](int c, uint32_t buf) {
        const int c0 = c * KC;
        int row = tid >> 2, j = tid & 3;
        int gr = n0 + (row < rem ? row : rem - 1);
        uint32_t dst = sbase + buf + (uint32_t)(row * 80 + j * 16);
        cpa16(dst, (const char*)(Ah + (size_t)gr * K1 + c0) + j * 16);
        cpa16(dst + APL, (const char*)(Al + (size_t)gr * K1 + c0) + j * 16);
    };
    // stage B1 of chunk c (weights, single plane; independent of producer)
    auto stageB = [&](int c, uint32_t buf) {
        const int c0 = c * KC;
        constexpr int G8 = N1 / 8;                 // 16B groups per row
        #pragma unroll
        for (int it = 0; it < KC * G8 / 256; it++) {
            int idx = it * 256 + tid;
            int row = idx / G8, g = idx - row * G8;
            uint32_t dst = sbase + buf + ABUF + (uint32_t)(row * (SB1 * 2) + g * 16);
            cpa16(dst, (const char*)(B1f + (size_t)(c0 + row) * N1) + g * 16);
        }
    };
    auto stage2 = [&](int c, uint32_t buf) {
        const int c0 = c * KC;
        constexpr int G8 = N2 / 8;
        #pragma unroll
        for (int it = 0; it < (KC * G8 + 255) / 256; it++) {
            int idx = it * 256 + tid;
            if (KC * G8 % 256 == 0 || idx < KC * G8) {
                int row = idx / G8, g = idx - row * G8;
                uint32_t dst = sbase + buf + (uint32_t)(row * (SB2 * 2) + g * 16);
                cpa16(dst, (const char*)(B2f + (size_t)(c0 + row) * N2) + g * 16);
            }
        }
        CP_COMMIT();
    };

    // PDL prologue: stage chunk-0 weights while the producer finishes.
    stageB(0, BUF0);
    cudaGridDependencySynchronize();               // A-operand now visible
    stageA(0, BUF0);
    CP_COMMIT();

    // =========================== phase 1 ===========================
    {
        const int col0 = wn * WC1;
        float acc[2][NT1][4];
        #pragma unroll
        for (int mt = 0; mt < 2; mt++)
            #pragma unroll
            for (int j = 0; j < NT1; j++)
                #pragma unroll
                for (int q = 0; q < 4; q++) acc[mt][j][q] = 0.f;

        for (int c = 0; c < NCH1; c++) {
            if (c + 1 < NCH1) {
                uint32_t nb = (c + 1) & 1 ? BUF1 : BUF0;
                stageB(c + 1, nb);
                stageA(c + 1, nb);
                CP_COMMIT();
                CP_WAIT1();
            } else {
                CP_WAIT0();
            }
            __syncthreads();

            const uint32_t buf = (c & 1) ? BUF1 : BUF0;
            #pragma unroll
            for (int kk = 0; kk < KC; kk += 16) {
                uint32_t ah[2][4], al[2][4];
                #pragma unroll
                for (int mt = 0; mt < 2; mt++) {
                    uint32_t ra = sbase + buf +
                        (uint32_t)((32 * wm + 16 * mt + lrow) * 80 + kk * 2 + lhalf * 16);
                    ldsm_x4(ah[mt], ra);
                    ldsm_x4(al[mt], ra + APL);
                }
                #pragma unroll
                for (int ng = 0; ng < NTG1; ng++) {
                    uint32_t rb = sbase + buf + ABUF +
                        (uint32_t)(((kk + lrow) * SB1 + col0 + ng * 16) * 2 + lhalf * 16);
                    uint32_t bh[4];
                    ldsm_x4t(bh, rb);
                    #pragma unroll
                    for (int mt = 0; mt < 2; mt++) {
                        mma_f16(acc[mt][2 * ng],     ah[mt], bh[0], bh[1]);
                        mma_f16(acc[mt][2 * ng],     al[mt], bh[0], bh[1]);
                        mma_f16(acc[mt][2 * ng + 1], ah[mt], bh[2], bh[3]);
                        mma_f16(acc[mt][2 * ng + 1], al[mt], bh[2], bh[3]);
                    }
                }
            }
            __syncthreads();   // buffer free for restage / epilogue aliasing
        }

        // overlap: issue phase2 chunk 0 stage (BUF0 region is dead now)
        stage2(0, P2B0);

        // epilogue -> h smem planes (relu + fp16 split); overwrites BUF1
        #pragma unroll
        for (int mt = 0; mt < 2; mt++) {
            int row0 = 32 * wm + 16 * mt + qr;
            #pragma unroll
            for (int j = 0; j < NT1; j++) {
                int col = col0 + 8 * j + qc;
                float b0 = __ldg(&bias1[col]), b1 = __ldg(&bias1[col + 1]);
                float v00 = fmaxf(acc[mt][j][0] + b0, 0.f);
                float v01 = fmaxf(acc[mt][j][1] + b1, 0.f);
                float v10 = fmaxf(acc[mt][j][2] + b0, 0.f);
                float v11 = fmaxf(acc[mt][j][3] + b1, 0.f);
                uint32_t hp, lp;
                uint32_t o0 = (uint32_t)((row0 * HST + col) * 2);
                split_pair(v00, v01, hp, lp);
                *(uint32_t*)(dsm + o0) = hp;
                *(uint32_t*)(dsm + HPL + o0) = lp;
                uint32_t o1 = o0 + (uint32_t)(8 * HST * 2);
                split_pair(v10, v11, hp, lp);
                *(uint32_t*)(dsm + o1) = hp;
                *(uint32_t*)(dsm + HPL + o1) = lp;
            }
        }
    }
    __syncthreads();

    // =========================== phase 2 ===========================
    {
        const int col0 = wn * WC2;
        float acc[2][NT2][4];
        #pragma unroll
        for (int mt = 0; mt < 2; mt++)
            #pragma unroll
            for (int j = 0; j < NT2; j++)
                #pragma unroll
                for (int q = 0; q < 4; q++) acc[mt][j][q] = 0.f;

        for (int c = 0; c < NCH2; c++) {
            if (c + 1 < NCH2) {
                stage2(c + 1, (c + 1) & 1 ? P2B1 : P2B0);
                CP_WAIT1();
            } else {
                CP_WAIT0();
            }
            __syncthreads();

            const uint32_t buf = (c & 1) ? P2B1 : P2B0;
            const int c0 = c * KC;
            #pragma unroll
            for (int kk = 0; kk < KC; kk += 16) {
                uint32_t ah[2][4], al[2][4];
                #pragma unroll
                for (int mt = 0; mt < 2; mt++) {
                    uint32_t ra = sbase +
                        (uint32_t)(((32 * wm + 16 * mt + lrow) * HST + c0 + kk) * 2 + lhalf * 16);
                    ldsm_x4(ah[mt], ra);
                    ldsm_x4(al[mt], ra + HPL);
                }
                #pragma unroll
                for (int ng = 0; ng < NTG2; ng++) {
                    uint32_t rb = sbase + buf +
                        (uint32_t)(((kk + lrow) * SB2 + col0 + ng * 16) * 2 + lhalf * 16);
                    uint32_t bh[4];
                    ldsm_x4t(bh, rb);
                    #pragma unroll
                    for (int mt = 0; mt < 2; mt++) {
                        mma_f16(acc[mt][2 * ng],     ah[mt], bh[0], bh[1]);
                        mma_f16(acc[mt][2 * ng],     al[mt], bh[0], bh[1]);
                        mma_f16(acc[mt][2 * ng + 1], ah[mt], bh[2], bh[3]);
                        mma_f16(acc[mt][2 * ng + 1], al[mt], bh[2], bh[3]);
                    }
                }
            }
            if (c + 1 < NCH2) __syncthreads();
        }

        // epilogue -> global fp32
        #pragma unroll
        for (int mt = 0; mt < 2; mt++) {
            int row0 = 32 * wm + 16 * mt + qr;
            int row1 = row0 + 8;
            #pragma unroll
            for (int j = 0; j < NT2; j++) {
                int col = col0 + 8 * j + qc;
                float b0 = __ldg(&bias2[col]), b1 = __ldg(&bias2[col + 1]);
                float v00 = acc[mt][j][0] + b0, v01 = acc[mt][j][1] + b1;
                float v10 = acc[mt][j][2] + b0, v11 = acc[mt][j][3] + b1;
                if (row0 < rem)
                    *(float2*)(Cf + (size_t)(n0 + row0) * N2 + col) = make_float2(v00, v01);
                if (row1 < rem)
                    *(float2*)(Cf + (size_t)(n0 + row1) * N2 + col) = make_float2(v10, v11);
            }
        }
    }
}

// ------------------------------- launcher ----------------------------------
extern "C" void kernel_launch(void* const* d_in, const int* in_sizes, int n_in,
                              void* d_out, int out_size) {
    const float* x   = (const float*)d_in[0];
    const int*   ei  = (const int*)d_in[1];
    const float* c1W = (const float*)d_in[2];
    const float* c1r = (const float*)d_in[3];
    const float* c1b = (const float*)d_in[4];
    const float* c2W = (const float*)d_in[5];
    const float* c2r = (const float*)d_in[6];
    const float* c2b = (const float*)d_in[7];
    const float* dw1 = (const float*)d_in[8];
    const float* db1 = (const float*)d_in[9];
    const float* dw2 = (const float*)d_in[10];
    const float* db2 = (const float*)d_in[11];
    float* out = (float*)d_out;

    void *pB2c, *pW;
    void *pA1h, *pA1l, *pZh, *pZl;
    void *pB1f, *pB2f, *pD1f, *pD2f;
    cudaGetSymbolAddress(&pB2c, g_b2c);
    cudaGetSymbolAddress(&pW, g_w);
    cudaGetSymbolAddress(&pA1h, g_A1h); cudaGetSymbolAddress(&pA1l, g_A1l);
    cudaGetSymbolAddress(&pZh, g_zh);   cudaGetSymbolAddress(&pZl, g_zl);
    cudaGetSymbolAddress(&pB1f, g_B1f); cudaGetSymbolAddress(&pB2f, g_B2f);
    cudaGetSymbolAddress(&pD1f, g_D1f); cudaGetSymbolAddress(&pD2f, g_D2f);

    // smem: h planes 67584 + stage buf0 (A 10240 + B1 16896) = 94720 -> occ 2
    const int SM_F = 67584 + 10240 + 16896;
    cudaFuncSetAttribute(fused2_k<128, 256, 256, 128>,
                         cudaFuncAttributeMaxDynamicSharedMemorySize, SM_F);
    cudaFuncSetAttribute(fused2_k<64, 256, 256, 64>,
                         cudaFuncAttributeMaxDynamicSharedMemorySize, SM_F);

    const int nFG = (NNODES + 63) / 64;                 // 782
    const int nE4Blocks = (NEDGES / 4 + 255) / 256;     // 782
    const int nAggBlocks = (NNODES * 32 + 255) / 256;   // 6250

    // PDL launch config: allow overlap with previous kernel in stream;
    // consumers order themselves via cudaGridDependencySynchronize().
    cudaLaunchAttribute at[1];
    at[0].id = cudaLaunchAttributeProgrammaticStreamSerialization;
    at[0].val.programmaticStreamSerializationAllowed = 1;
    cudaLaunchConfig_t cfg{};
    cfg.blockDim = {256, 1, 1};
    cfg.attrs = at;
    cfg.numAttrs = 1;

    // --- CSR build + weight prep ---
    cfg.gridDim = {NHIST_BLK + NPREP_BLK, 1, 1};
    cfg.dynamicSmemBytes = 0;
    cudaLaunchKernelEx(&cfg, histprep_k, ei, c1W, c1r, c2W, c2r, c2b, dw1, dw2);
    {
        cudaLaunchConfig_t c2 = cfg;
        c2.gridDim = {NB_SCAN, 1, 1};
        c2.blockDim = {1024, 1, 1};
        cudaLaunchKernelEx(&c2, scanm_k);
    }
    cfg.gridDim = {(unsigned)nE4Blocks, 1, 1};
    cudaLaunchKernelEx(&cfg, place_k, ei);

    // --- conv1 input aggregation ---
    cfg.gridDim = {(unsigned)nAggBlocks, 1, 1};
    cudaLaunchKernelEx(&cfg, agg1_k, x);

    // --- fused conv1 GEMM + conv2 weight GEMM: A1 -> h(smem) -> hWr (fp32) ---
    cfg.gridDim = {(unsigned)nFG, 1, 1};
    cfg.dynamicSmemBytes = SM_F;
    cudaLaunchKernelEx(&cfg, fused2_k<128, 256, 256, 128>,
        (const __half*)pA1h, (const __half*)pA1l,
        (const __half*)pB1f, (const float*)c1b,
        (const __half*)pB2f, (const float*)pB2c,
        (float*)pW, (int)NNODES);

    // --- conv2 aggregation -> z planes ---
    cfg.gridDim = {(unsigned)nAggBlocks, 1, 1};
    cfg.dynamicSmemBytes = 0;
    cudaLaunchKernelEx(&cfg, agg2_k);

    // --- fused decoder: z -> h2(smem) -> out ---
    cfg.gridDim = {(unsigned)nFG, 1, 1};
    cfg.dynamicSmemBytes = SM_F;
    cudaLaunchKernelEx(&cfg, fused2_k<64, 256, 256, 64>,
        (const __half*)pZh, (const __half*)pZl,
        (const __half*)pD1f, (const float*)db1,
        (const __half*)pD2f, (const float*)db2,
        out, (int)NNODES);
}

// round 16
// speedup vs baseline: 1.3307x; 1.0308x over previous
#include <cuda_runtime.h>
#include <cuda_fp16.h>
#include <math.h>
#include <stdint.h>

// ---------------------------------------------------------------------------
// GraphAE on GB300 (sm_103 plain target -> mma.sync tensor path).
// pseudo == 0 => only spline weight k=0 contributes.
// Activations: A1/h as fp16 hi/lo pairs (22-bit); hW and z single fp16
// (spent precision: weights fp16 + hW fp16 + z fp16 ~ 5e-4 total, < 1e-3).
// GEMMs: fp16 mma.sync, fp32 accum; dual-plane A = 2 MMAs, single = 1.
// Pipeline (7 launches, PDL-chained):
//   hist+prep -> scanm -> place -> agg1 -> FUSED[G1+G2] -> agg2
//   -> FUSED[G3+G4]
// ---------------------------------------------------------------------------

#define NNODES 50000
#define NEDGES 800000
#define NB_SCAN 49
#define NHIST_BLK 782          // blocks doing histogram (4 edges/thread)
#define NPREP_BLK 128          // blocks doing weight prep

// ------------------------- scratch (static device) -------------------------
__device__ int   g_cnt[NNODES];        // zero-init (BSS); scanm restores zero
__device__ int   g_rowptr[NNODES + 1];
__device__ int   g_cursor[NNODES];
__device__ int   g_csr[NEDGES];
__device__ float g_invdeg[NNODES];
__device__ int   g_bflag[NB_SCAN];     // scan aggregates (sentinel +1); place zeroes

// activation storage
__device__ __half g_A1h[(size_t)NNODES * 128], g_A1l[(size_t)NNODES * 128];
__device__ __half g_wh[(size_t)NNODES * 64];   // h@W2 (fp16)
__device__ float  g_wr[(size_t)NNODES * 64];   // h@root2 + b2 (fp32)
__device__ __half g_z[(size_t)NNODES * 64];    // conv2 output (fp16)

// fp16 weights, natural [k][n] row-major (single plane)
__device__ __half g_B1f[128 * 256];
__device__ __half g_B2f[256 * 128];
__device__ __half g_D1f[64 * 256];
__device__ __half g_D2f[256 * 64];
__device__ float g_b2c[128];                   // [0 | conv2_b]

// ------------------------------ helpers ------------------------------------
__device__ __forceinline__ uint32_t smem_u32(const void* p) {
    uint32_t a;
    asm("{ .reg .u64 t; cvta.to.shared.u64 t, %1; cvt.u32.u64 %0, t; }"
        : "=r"(a) : "l"(p));
    return a;
}
__device__ __forceinline__ void ldsm_x4(uint32_t* r, uint32_t addr) {
    asm volatile("ldmatrix.sync.aligned.m8n8.x4.shared.b16 {%0,%1,%2,%3}, [%4];"
                 : "=r"(r[0]), "=r"(r[1]), "=r"(r[2]), "=r"(r[3]) : "r"(addr));
}
__device__ __forceinline__ void ldsm_x4t(uint32_t* r, uint32_t addr) {
    asm volatile("ldmatrix.sync.aligned.m8n8.x4.trans.shared.b16 {%0,%1,%2,%3}, [%4];"
                 : "=r"(r[0]), "=r"(r[1]), "=r"(r[2]), "=r"(r[3]) : "r"(addr));
}
__device__ __forceinline__ void mma_f16(float* d, const uint32_t* a,
                                        uint32_t b0, uint32_t b1) {
    asm volatile("mma.sync.aligned.m16n8k16.row.col.f32.f16.f16.f32 "
                 "{%0,%1,%2,%3}, {%4,%5,%6,%7}, {%8,%9}, {%0,%1,%2,%3};"
                 : "+f"(d[0]), "+f"(d[1]), "+f"(d[2]), "+f"(d[3])
                 : "r"(a[0]), "r"(a[1]), "r"(a[2]), "r"(a[3]), "r"(b0), "r"(b1));
}
__device__ __forceinline__ void cpa16(uint32_t dst, const void* src) {
    asm volatile("cp.async.cg.shared.global [%0], [%1], 16;"
                 :: "r"(dst), "l"(src));
}
#define CP_COMMIT() asm volatile("cp.async.commit_group;" ::: "memory")
#define CP_WAIT0()  asm volatile("cp.async.wait_group 0;" ::: "memory")
#define CP_WAIT1()  asm volatile("cp.async.wait_group 1;" ::: "memory")

__device__ __forceinline__ void split1(float v, uint16_t& h, uint16_t& l) {
    __half hh = __float2half_rn(v);
    float r = v - __half2float(hh);
    __half hl = __float2half_rn(r);
    h = __half_as_ushort(hh);
    l = __half_as_ushort(hl);
}
__device__ __forceinline__ void split_pair(float a, float b, uint32_t& hp, uint32_t& lp) {
    uint16_t h0, l0, h1, l1;
    split1(a, h0, l0); split1(b, h1, l1);
    hp = (uint32_t)h0 | ((uint32_t)h1 << 16);
    lp = (uint32_t)l0 | ((uint32_t)l1 << 16);
}
__device__ __forceinline__ uint32_t pack_h2(float a, float b) {
    return (uint32_t)__half_as_ushort(__float2half_rn(a)) |
           ((uint32_t)__half_as_ushort(__float2half_rn(b)) << 16);
}
__device__ __forceinline__ float2 h2f(uint32_t u) {
    __half2 t = *reinterpret_cast<__half2*>(&u);
    return __half22float2(t);
}

// --------------------- fused histogram + weight prep -----------------------
__global__ void histprep_k(const int* __restrict__ ei,
                           const float* __restrict__ c1W, const float* __restrict__ c1r,
                           const float* __restrict__ c2W, const float* __restrict__ c2r,
                           const float* __restrict__ c2b,
                           const float* __restrict__ dw1, const float* __restrict__ dw2) {
    if (blockIdx.x < NHIST_BLK) {
        int e4 = (blockIdx.x * blockDim.x + threadIdx.x) * 4;
        if (e4 < NEDGES) {
            int4 d = *(const int4*)(ei + NEDGES + e4);
            atomicAdd(&g_cnt[d.x], 1);
            atomicAdd(&g_cnt[d.y], 1);
            atomicAdd(&g_cnt[d.z], 1);
            atomicAdd(&g_cnt[d.w], 1);
        }
        return;
    }
    int i = (blockIdx.x - NHIST_BLK) * blockDim.x + threadIdx.x;
    if (i < 128 * 256) {  // B1 [k=128][n=256]
        int k = i >> 8, n = i & 255;
        float v = (k < 64) ? c1W[k * 256 + n] : c1r[(k - 64) * 256 + n];
        g_B1f[i] = __float2half_rn(v);
    }
    if (i < 256 * 128) {  // B2 [k=256][n=128]
        int k = i >> 7, n = i & 127;
        float v = (n < 64) ? c2W[k * 64 + n] : c2r[k * 64 + (n - 64)];
        g_B2f[i] = __float2half_rn(v);
    }
    if (i < 64 * 256)  g_D1f[i] = __float2half_rn(dw1[i]);
    if (i < 256 * 64)  g_D2f[i] = __float2half_rn(dw2[i]);
    if (i < 128) g_b2c[i] = (i < 64) ? 0.0f : c2b[i - 64];
}

// ------------------------------- CSR build ---------------------------------
__global__ void scanm_k() {
    cudaGridDependencySynchronize();           // need g_cnt from histprep
    __shared__ int wsum[32];
    __shared__ int s_boff;
    int blk = blockIdx.x, tid = threadIdx.x;
    int i = blk * 1024 + tid;
    int v = (i < NNODES) ? g_cnt[i] : 0;
    int incl = v;
    #pragma unroll
    for (int o = 1; o < 32; o <<= 1) {
        int t = __shfl_up_sync(0xffffffff, incl, o);
        if ((tid & 31) >= o) incl += t;
    }
    if ((tid & 31) == 31) wsum[tid >> 5] = incl;
    if (tid == 0) s_boff = 0;
    __syncthreads();
    if (tid < 32) {
        int w = wsum[tid];
        #pragma unroll
        for (int o = 1; o < 32; o <<= 1) {
            int t = __shfl_up_sync(0xffffffff, w, o);
            if (tid >= o) w += t;
        }
        wsum[tid] = w;                         // inclusive warp sums
    }
    __syncthreads();
    if (tid >= 32) incl += wsum[(tid >> 5) - 1];
    if (tid == 1023) atomicExch(&g_bflag[blk], wsum[31] + 1);  // publish total
    if (tid < blk) {                                           // poll predecessors
        int t;
        do { t = atomicAdd(&g_bflag[tid], 0); } while (t == 0);
        atomicAdd(&s_boff, t - 1);
    }
    __syncthreads();
    int boff = s_boff;
    if (i < NNODES) {
        int start = boff + incl - v;
        g_rowptr[i] = start;
        g_cursor[i] = start;
        g_invdeg[i] = 1.0f / fmaxf((float)v, 1.0f);
        g_cnt[i] = 0;                          // restore for next replay
        if (i == NNODES - 1) g_rowptr[NNODES] = boff + incl;
    }
}

__global__ void place_k(const int* __restrict__ ei) {
    int t = blockIdx.x * blockDim.x + threadIdx.x;
    int e4 = t * 4;
    int4 d, s;
    if (e4 < NEDGES) {                         // prologue: edge loads (input)
        d = *(const int4*)(ei + NEDGES + e4);
        s = *(const int4*)(ei + e4);
    }
    cudaGridDependencySynchronize();           // need g_cursor from scanm
    if (e4 < NEDGES) {
        g_csr[atomicAdd(&g_cursor[d.x], 1)] = s.x;
        g_csr[atomicAdd(&g_cursor[d.y], 1)] = s.y;
        g_csr[atomicAdd(&g_cursor[d.z], 1)] = s.z;
        g_csr[atomicAdd(&g_cursor[d.w], 1)] = s.w;
    }
    if (t < NB_SCAN) g_bflag[t] = 0;           // reset scan flags for next replay
}

// --------------------------- gather aggregations ---------------------------
// warp per node; lane owns feature pair (2*lane, 2*lane+1); simple loop.
__global__ void agg1_k(const float* __restrict__ x) {
    int gt = blockIdx.x * blockDim.x + threadIdx.x;
    int node = gt >> 5;
    int lane = gt & 31;
    float2 xv = make_float2(0.f, 0.f);
    if (node < NNODES)                          // prologue: own x row (input)
        xv = __ldg((const float2*)(x + (size_t)node * 64 + 2 * lane));
    cudaGridDependencySynchronize();            // need rowptr/csr from place
    if (node >= NNODES) return;
    int beg = g_rowptr[node], end = g_rowptr[node + 1];
    float s0 = 0.f, s1 = 0.f;
    for (int i = beg; i < end; i++) {
        int s = g_csr[i];
        float2 v = __ldg((const float2*)(x + (size_t)s * 64 + 2 * lane));
        s0 += v.x; s1 += v.y;
    }
    float iv = g_invdeg[node];
    uint32_t hp, lp;
    size_t o = (size_t)node * 128 + 2 * lane;
    split_pair(s0 * iv, s1 * iv, hp, lp);
    *(uint32_t*)(g_A1h + o) = hp; *(uint32_t*)(g_A1l + o) = lp;
    split_pair(xv.x, xv.y, hp, lp);
    *(uint32_t*)(g_A1h + o + 64) = hp; *(uint32_t*)(g_A1l + o + 64) = lp;
}

// z = gather(hW fp16)*invdeg + hroot(fp32) -> fp16 z.
__global__ void agg2_k() {
    cudaGridDependencySynchronize();            // need g_wh/g_wr from fused1
    int gt = blockIdx.x * blockDim.x + threadIdx.x;
    int node = gt >> 5;
    if (node >= NNODES) return;
    int lane = gt & 31;
    int beg = g_rowptr[node], end = g_rowptr[node + 1];
    float s0 = 0.f, s1 = 0.f;
    for (int i = beg; i < end; i++) {
        int s = g_csr[i];
        float2 v = h2f(__ldg((const uint32_t*)(g_wh + (size_t)s * 64 + 2 * lane)));
        s0 += v.x; s1 += v.y;
    }
    float iv = g_invdeg[node];
    float2 r = __ldg((const float2*)(g_wr + (size_t)node * 64 + 2 * lane));
    size_t zo = (size_t)node * 64 + 2 * lane;
    *(uint32_t*)(g_z + zo) = pack_h2(s0 * iv + r.x, s1 * iv + r.y);
}

// -------------------- fused two-GEMM kernel (64-row tile) ------------------
// Phase1: T = relu(A[64,K1] @ B1[K1,N1=256] + bias1) -> split -> h smem
// Phase2: out = T @ B2[K2=N1,N2] + bias2.
// ADUAL: A is a hi/lo plane pair (2 MMAs) vs single plane (1 MMA).
// SPLITW: phase2 epilogue writes cols<64 as fp16 (Wh) and cols>=64 as fp32
//         root (Cf, offset col-64); otherwise plain fp32 Cf[N2].
template <int K1, int N1, int K2, int N2, bool ADUAL, bool SPLITW>
__global__ void __launch_bounds__(256, 2)
fused2_k(const __half* __restrict__ Ah, const __half* __restrict__ Al,
         const __half* __restrict__ B1f, const float* __restrict__ bias1,
         const __half* __restrict__ B2f, const float* __restrict__ bias2,
         float* __restrict__ Cf, __half* __restrict__ Wh, int nRows) {
    static_assert(N1 == 256 && K2 == N1, "layout assumes N1=256");
    constexpr int KC = 32;
    constexpr int NCH1 = K1 / KC, NCH2 = K2 / KC;
    static_assert(NCH1 % 2 == 0, "last phase1 chunk must land in buf1");
    constexpr int WC1 = N1 / 4, NT1 = WC1 / 8, NTG1 = WC1 / 16;
    constexpr int WC2 = N2 / 4, NT2 = WC2 / 8, NTG2 = WC2 / 16;
    constexpr int SB1 = N1 + 8, SB2 = N2 + 8;
    constexpr int HST = 264;                       // h smem row stride (elems)
    constexpr int HPL = 64 * HST * 2;              // 33792 bytes per h plane
    constexpr int APL = 64 * 40 * 2;               // 5120 per A plane
    constexpr int ABUF = (ADUAL ? 2 : 1) * APL;
    constexpr int SBB1 = KC * SB1 * 2;             // B1 plane bytes (16896)
    constexpr int SBB2 = KC * SB2 * 2;
    constexpr int BUF0 = 2 * HPL;                  // 67584 (stage region)
    constexpr int BUF1 = 0;                        // aliases h planes (phase1)
    constexpr int P2B0 = BUF0;                     // phase2 B2 buffers
    constexpr int P2B1 = BUF0 + SBB2;

    extern __shared__ char dsm[];
    uint32_t sbase = smem_u32(dsm);

    const int tid = threadIdx.x;
    const int wid = tid >> 5, lane = tid & 31;
    const int wm = wid & 1, wn = wid >> 1;
    const int n0 = blockIdx.x * 64;
    int rem = nRows - n0;
    if (rem > 64) rem = 64;

    const int lrow = lane & 15, lhalf = lane >> 4;
    const int qr = lane >> 2, qc = (lane & 3) << 1;

    // stage A of chunk c (depends on producer output)
    auto stageA = [&](int c, uint32_t buf) {
        const int c0 = c * KC;
        int row = tid >> 2, j = tid & 3;
        int gr = n0 + (row < rem ? row : rem - 1);
        uint32_t dst = sbase + buf + (uint32_t)(row * 80 + j * 16);
        cpa16(dst, (const char*)(Ah + (size_t)gr * K1 + c0) + j * 16);
        if (ADUAL)
            cpa16(dst + APL, (const char*)(Al + (size_t)gr * K1 + c0) + j * 16);
    };
    // stage B1 of chunk c (weights; independent of producer)
    auto stageB = [&](int c, uint32_t buf) {
        const int c0 = c * KC;
        constexpr int G8 = N1 / 8;                 // 16B groups per row
        #pragma unroll
        for (int it = 0; it < KC * G8 / 256; it++) {
            int idx = it * 256 + tid;
            int row = idx / G8, g = idx - row * G8;
            uint32_t dst = sbase + buf + ABUF + (uint32_t)(row * (SB1 * 2) + g * 16);
            cpa16(dst, (const char*)(B1f + (size_t)(c0 + row) * N1) + g * 16);
        }
    };
    auto stage2 = [&](int c, uint32_t buf) {
        const int c0 = c * KC;
        constexpr int G8 = N2 / 8;
        #pragma unroll
        for (int it = 0; it < (KC * G8 + 255) / 256; it++) {
            int idx = it * 256 + tid;
            if (KC * G8 % 256 == 0 || idx < KC * G8) {
                int row = idx / G8, g = idx - row * G8;
                uint32_t dst = sbase + buf + (uint32_t)(row * (SB2 * 2) + g * 16);
                cpa16(dst, (const char*)(B2f + (size_t)(c0 + row) * N2) + g * 16);
            }
        }
        CP_COMMIT();
    };

    // PDL prologue: stage chunk-0 weights while the producer finishes.
    stageB(0, BUF0);
    cudaGridDependencySynchronize();               // A-operand now visible
    stageA(0, BUF0);
    CP_COMMIT();

    // =========================== phase 1 ===========================
    {
        const int col0 = wn * WC1;
        float acc[2][NT1][4];
        #pragma unroll
        for (int mt = 0; mt < 2; mt++)
            #pragma unroll
            for (int j = 0; j < NT1; j++)
                #pragma unroll
                for (int q = 0; q < 4; q++) acc[mt][j][q] = 0.f;

        for (int c = 0; c < NCH1; c++) {
            if (c + 1 < NCH1) {
                uint32_t nb = (c + 1) & 1 ? BUF1 : BUF0;
                stageB(c + 1, nb);
                stageA(c + 1, nb);
                CP_COMMIT();
                CP_WAIT1();
            } else {
                CP_WAIT0();
            }
            __syncthreads();

            const uint32_t buf = (c & 1) ? BUF1 : BUF0;
            #pragma unroll
            for (int kk = 0; kk < KC; kk += 16) {
                uint32_t ah[2][4], al[2][4];
                #pragma unroll
                for (int mt = 0; mt < 2; mt++) {
                    uint32_t ra = sbase + buf +
                        (uint32_t)((32 * wm + 16 * mt + lrow) * 80 + kk * 2 + lhalf * 16);
                    ldsm_x4(ah[mt], ra);
                    if (ADUAL) ldsm_x4(al[mt], ra + APL);
                }
                #pragma unroll
                for (int ng = 0; ng < NTG1; ng++) {
                    uint32_t rb = sbase + buf + ABUF +
                        (uint32_t)(((kk + lrow) * SB1 + col0 + ng * 16) * 2 + lhalf * 16);
                    uint32_t bh[4];
                    ldsm_x4t(bh, rb);
                    #pragma unroll
                    for (int mt = 0; mt < 2; mt++) {
                        mma_f16(acc[mt][2 * ng],     ah[mt], bh[0], bh[1]);
                        if (ADUAL) mma_f16(acc[mt][2 * ng], al[mt], bh[0], bh[1]);
                        mma_f16(acc[mt][2 * ng + 1], ah[mt], bh[2], bh[3]);
                        if (ADUAL) mma_f16(acc[mt][2 * ng + 1], al[mt], bh[2], bh[3]);
                    }
                }
            }
            __syncthreads();   // buffer free for restage / epilogue aliasing
        }

        // overlap: issue phase2 chunk 0 stage (BUF0 region is dead now)
        stage2(0, P2B0);

        // epilogue -> h smem planes (relu + fp16 split); overwrites BUF1
        #pragma unroll
        for (int mt = 0; mt < 2; mt++) {
            int row0 = 32 * wm + 16 * mt + qr;
            #pragma unroll
            for (int j = 0; j < NT1; j++) {
                int col = col0 + 8 * j + qc;
                float b0 = __ldg(&bias1[col]), b1 = __ldg(&bias1[col + 1]);
                float v00 = fmaxf(acc[mt][j][0] + b0, 0.f);
                float v01 = fmaxf(acc[mt][j][1] + b1, 0.f);
                float v10 = fmaxf(acc[mt][j][2] + b0, 0.f);
                float v11 = fmaxf(acc[mt][j][3] + b1, 0.f);
                uint32_t hp, lp;
                uint32_t o0 = (uint32_t)((row0 * HST + col) * 2);
                split_pair(v00, v01, hp, lp);
                *(uint32_t*)(dsm + o0) = hp;
                *(uint32_t*)(dsm + HPL + o0) = lp;
                uint32_t o1 = o0 + (uint32_t)(8 * HST * 2);
                split_pair(v10, v11, hp, lp);
                *(uint32_t*)(dsm + o1) = hp;
                *(uint32_t*)(dsm + HPL + o1) = lp;
            }
        }
    }
    __syncthreads();

    // =========================== phase 2 ===========================
    {
        const int col0 = wn * WC2;
        float acc[2][NT2][4];
        #pragma unroll
        for (int mt = 0; mt < 2; mt++)
            #pragma unroll
            for (int j = 0; j < NT2; j++)
                #pragma unroll
                for (int q = 0; q < 4; q++) acc[mt][j][q] = 0.f;

        for (int c = 0; c < NCH2; c++) {
            if (c + 1 < NCH2) {
                stage2(c + 1, (c + 1) & 1 ? P2B1 : P2B0);
                CP_WAIT1();
            } else {
                CP_WAIT0();
            }
            __syncthreads();

            const uint32_t buf = (c & 1) ? P2B1 : P2B0;
            const int c0 = c * KC;
            #pragma unroll
            for (int kk = 0; kk < KC; kk += 16) {
                uint32_t ah[2][4], al[2][4];
                #pragma unroll
                for (int mt = 0; mt < 2; mt++) {
                    uint32_t ra = sbase +
                        (uint32_t)(((32 * wm + 16 * mt + lrow) * HST + c0 + kk) * 2 + lhalf * 16);
                    ldsm_x4(ah[mt], ra);
                    ldsm_x4(al[mt], ra + HPL);
                }
                #pragma unroll
                for (int ng = 0; ng < NTG2; ng++) {
                    uint32_t rb = sbase + buf +
                        (uint32_t)(((kk + lrow) * SB2 + col0 + ng * 16) * 2 + lhalf * 16);
                    uint32_t bh[4];
                    ldsm_x4t(bh, rb);
                    #pragma unroll
                    for (int mt = 0; mt < 2; mt++) {
                        mma_f16(acc[mt][2 * ng],     ah[mt], bh[0], bh[1]);
                        mma_f16(acc[mt][2 * ng],     al[mt], bh[0], bh[1]);
                        mma_f16(acc[mt][2 * ng + 1], ah[mt], bh[2], bh[3]);
                        mma_f16(acc[mt][2 * ng + 1], al[mt], bh[2], bh[3]);
                    }
                }
            }
            if (c + 1 < NCH2) __syncthreads();
        }

        // epilogue -> global
        #pragma unroll
        for (int mt = 0; mt < 2; mt++) {
            int row0 = 32 * wm + 16 * mt + qr;
            int row1 = row0 + 8;
            #pragma unroll
            for (int j = 0; j < NT2; j++) {
                int col = col0 + 8 * j + qc;
                float b0 = __ldg(&bias2[col]), b1 = __ldg(&bias2[col + 1]);
                float v00 = acc[mt][j][0] + b0, v01 = acc[mt][j][1] + b1;
                float v10 = acc[mt][j][2] + b0, v11 = acc[mt][j][3] + b1;
                if (SPLITW) {
                    if (col < 64) {                 // hW part -> fp16 Wh
                        if (row0 < rem)
                            *(uint32_t*)(Wh + (size_t)(n0 + row0) * 64 + col) =
                                pack_h2(v00, v01);
                        if (row1 < rem)
                            *(uint32_t*)(Wh + (size_t)(n0 + row1) * 64 + col) =
                                pack_h2(v10, v11);
                    } else {                        // root part -> fp32 Cf
                        int rc = col - 64;
                        if (row0 < rem)
                            *(float2*)(Cf + (size_t)(n0 + row0) * 64 + rc) =
                                make_float2(v00, v01);
                        if (row1 < rem)
                            *(float2*)(Cf + (size_t)(n0 + row1) * 64 + rc) =
                                make_float2(v10, v11);
                    }
                } else {
                    if (row0 < rem)
                        *(float2*)(Cf + (size_t)(n0 + row0) * N2 + col) = make_float2(v00, v01);
                    if (row1 < rem)
                        *(float2*)(Cf + (size_t)(n0 + row1) * N2 + col) = make_float2(v10, v11);
                }
            }
        }
    }
}

// ------------------------------- launcher ----------------------------------
extern "C" void kernel_launch(void* const* d_in, const int* in_sizes, int n_in,
                              void* d_out, int out_size) {
    const float* x   = (const float*)d_in[0];
    const int*   ei  = (const int*)d_in[1];
    const float* c1W = (const float*)d_in[2];
    const float* c1r = (const float*)d_in[3];
    const float* c1b = (const float*)d_in[4];
    const float* c2W = (const float*)d_in[5];
    const float* c2r = (const float*)d_in[6];
    const float* c2b = (const float*)d_in[7];
    const float* dw1 = (const float*)d_in[8];
    const float* db1 = (const float*)d_in[9];
    const float* dw2 = (const float*)d_in[10];
    const float* db2 = (const float*)d_in[11];
    float* out = (float*)d_out;

    void *pB2c, *pWh, *pWr, *pZ;
    void *pA1h, *pA1l;
    void *pB1f, *pB2f, *pD1f, *pD2f;
    cudaGetSymbolAddress(&pB2c, g_b2c);
    cudaGetSymbolAddress(&pWh, g_wh);   cudaGetSymbolAddress(&pWr, g_wr);
    cudaGetSymbolAddress(&pZ, g_z);
    cudaGetSymbolAddress(&pA1h, g_A1h); cudaGetSymbolAddress(&pA1l, g_A1l);
    cudaGetSymbolAddress(&pB1f, g_B1f); cudaGetSymbolAddress(&pB2f, g_B2f);
    cudaGetSymbolAddress(&pD1f, g_D1f); cudaGetSymbolAddress(&pD2f, g_D2f);

    // smem: h planes 67584 + stage buf0 (A + B1 16896)
    const int SM_F1 = 67584 + 2 * 5120 + 16896;  // 94720 (dual A planes)
    const int SM_F2 = 67584 + 5120 + 16896;      // 89600 (single A plane)
    cudaFuncSetAttribute((void*)fused2_k<128, 256, 256, 128, true, true>,
                         cudaFuncAttributeMaxDynamicSharedMemorySize, SM_F1);
    cudaFuncSetAttribute((void*)fused2_k<64, 256, 256, 64, false, false>,
                         cudaFuncAttributeMaxDynamicSharedMemorySize, SM_F2);

    const int nFG = (NNODES + 63) / 64;                 // 782
    const int nE4Blocks = (NEDGES / 4 + 255) / 256;     // 782
    const int nAggBlocks = (NNODES * 32 + 255) / 256;   // 6250

    // PDL launch config
    cudaLaunchAttribute at[1];
    at[0].id = cudaLaunchAttributeProgrammaticStreamSerialization;
    at[0].val.programmaticStreamSerializationAllowed = 1;
    cudaLaunchConfig_t cfg{};
    cfg.blockDim = {256, 1, 1};
    cfg.attrs = at;
    cfg.numAttrs = 1;

    // --- CSR build + weight prep ---
    cfg.gridDim = {NHIST_BLK + NPREP_BLK, 1, 1};
    cfg.dynamicSmemBytes = 0;
    cudaLaunchKernelEx(&cfg, histprep_k, ei, c1W, c1r, c2W, c2r, c2b, dw1, dw2);
    {
        cudaLaunchConfig_t c2 = cfg;
        c2.gridDim = {NB_SCAN, 1, 1};
        c2.blockDim = {1024, 1, 1};
        cudaLaunchKernelEx(&c2, scanm_k);
    }
    cfg.gridDim = {(unsigned)nE4Blocks, 1, 1};
    cudaLaunchKernelEx(&cfg, place_k, ei);

    // --- conv1 input aggregation ---
    cfg.gridDim = {(unsigned)nAggBlocks, 1, 1};
    cudaLaunchKernelEx(&cfg, agg1_k, x);

    // --- fused conv1 GEMM + conv2 weight GEMM: A1 -> h(smem) -> wh/wr ---
    cfg.gridDim = {(unsigned)nFG, 1, 1};
    cfg.dynamicSmemBytes = SM_F1;
    cudaLaunchKernelEx(&cfg, fused2_k<128, 256, 256, 128, true, true>,
        (const __half*)pA1h, (const __half*)pA1l,
        (const __half*)pB1f, (const float*)c1b,
        (const __half*)pB2f, (const float*)pB2c,
        (float*)pWr, (__half*)pWh, (int)NNODES);

    // --- conv2 aggregation -> z (fp16) ---
    cfg.gridDim = {(unsigned)nAggBlocks, 1, 1};
    cfg.dynamicSmemBytes = 0;
    cudaLaunchKernelEx(&cfg, agg2_k);

    // --- fused decoder: z -> h2(smem) -> out ---
    cfg.gridDim = {(unsigned)nFG, 1, 1};
    cfg.dynamicSmemBytes = SM_F2;
    cudaLaunchKernelEx(&cfg, fused2_k<64, 256, 256, 64, false, false>,
        (const __half*)pZ, (const __half*)nullptr,
        (const __half*)pD1f, (const float*)db1,
        (const __half*)pD2f, (const float*)db2,
        out, (__half*)nullptr, (int)NNODES);
}